// round 12
// baseline (speedup 1.0000x reference)
#include <cuda_runtime.h>
#include <cuda_bf16.h>
#include <math.h>
#include <stdint.h>

#define S1_N (8*64*64*64)
#define S2_N (8*128*32*32)
#define S3_N (8*128*16*16)

__device__ float g_h1[S1_N], g_x1[S1_N], g_z1[S1_N], g_rh1[S1_N];
__device__ float g_h2[S2_N], g_x2[S2_N], g_z2[S2_N], g_rh2[S2_N];
__device__ float g_h3[S3_N], g_x3[S3_N], g_z3[S3_N], g_rh3[S3_N];

__device__ float g_wt_c2[64*16*128];
__device__ float g_wt_c3[128*16*128];

// bf16 hi/lo packed gate weights, column-permuted within each 32-oc block:
// gmem pos ((cb*25+k)*8+q)*Cout + ocblk*32 + (g*4+f)  holds  oc = ocblk*32 + g + f*8
__device__ unsigned g_wh_zr1[64*25*128],  g_wl_zr1[64*25*128];
__device__ unsigned g_wh_h1 [64*25*64],   g_wl_h1 [64*25*64];
__device__ unsigned g_wh_zr2[128*25*256], g_wl_zr2[128*25*256];
__device__ unsigned g_wh_h2 [128*25*128], g_wl_h2 [128*25*128];
__device__ unsigned g_wh_zr3[128*25*256], g_wl_zr3[128*25*256];
__device__ unsigned g_wh_h3 [128*25*128], g_wl_h3 [128*25*128];

typedef unsigned long long ull;

__device__ __forceinline__ ull pack2(float lo, float hi) {
    ull r; asm("mov.b64 %0, {%1, %2};" : "=l"(r) : "f"(lo), "f"(hi)); return r;
}
__device__ __forceinline__ void unpack2(ull v, float& lo, float& hi) {
    asm("mov.b64 {%0, %1}, %2;" : "=f"(lo), "=f"(hi) : "l"(v));
}
__device__ __forceinline__ ull ffma2(ull a, ull b, ull c) {
    ull d; asm("fma.rn.f32x2 %0, %1, %2, %3;" : "=l"(d) : "l"(a), "l"(b), "l"(c)); return d;
}
__device__ __forceinline__ float sigmoidf_(float v) { return 1.f / (1.f + expf(-v)); }

__device__ __forceinline__ void cp4(uint32_t dst, const float* src, bool p) {
    int sz = p ? 4 : 0;
    asm volatile("cp.async.ca.shared.global [%0], [%1], 4, %2;\n" :: "r"(dst), "l"(src), "r"(sz));
}
__device__ __forceinline__ void cp16(uint32_t dst, const void* src) {
    asm volatile("cp.async.cg.shared.global [%0], [%1], 16;\n" :: "r"(dst), "l"(src));
}
__device__ __forceinline__ void cp_commit() { asm volatile("cp.async.commit_group;\n"); }
template<int N> __device__ __forceinline__ void cp_wait() {
    asm volatile("cp.async.wait_group %0;\n" :: "n"(N));
}
__device__ __forceinline__ void mma16816(float* d, unsigned a0, unsigned a1,
                                         unsigned a2, unsigned a3, unsigned b0, unsigned b1) {
    asm("mma.sync.aligned.m16n8k16.row.col.f32.bf16.bf16.f32 "
        "{%0,%1,%2,%3}, {%4,%5,%6,%7}, {%8,%9}, {%0,%1,%2,%3};"
        : "+f"(d[0]), "+f"(d[1]), "+f"(d[2]), "+f"(d[3])
        : "r"(a0), "r"(a1), "r"(a2), "r"(a3), "r"(b0), "r"(b1));
}

__global__ void transpose_w_kernel(const float* __restrict__ w, float* __restrict__ wt,
                                   int Cin, int K, int Cout)
{
    int i = blockIdx.x * blockDim.x + threadIdx.x;
    if (i >= Cout * Cin * K) return;
    int oc = i / (Cin * K);
    int rem = i - oc * (Cin * K);
    int ci = rem / K, k = rem - (rem / K) * K;
    wt[(ci * K + k) * Cout + oc] = w[i];
}

// pack with column permutation: pos (g*4+f) in 32-block holds oc (g + f*8)
__global__ void wpack_kernel(const float* __restrict__ w, unsigned* __restrict__ whi,
                             unsigned* __restrict__ wlo, int Cin, int Cout)
{
    int i = blockIdx.x * blockDim.x + threadIdx.x;
    if (i >= (Cin / 2) * 25 * Cout) return;
    int ocpos = i % Cout;
    int pr = i / Cout;
    int cb = pr / 200, r2 = pr - cb * 200;
    int k = r2 >> 3, q = r2 & 7;
    int ch0 = cb * 16 + 2 * q;
    int ocblk = ocpos >> 5, c32 = ocpos & 31;
    int oc = ocblk * 32 + (c32 >> 2) + (c32 & 3) * 8;
    float w0 = w[(oc * Cin + ch0) * 25 + k];
    float w1 = w[(oc * Cin + ch0 + 1) * 25 + k];
    unsigned hp; asm("cvt.rn.bf16x2.f32 %0, %1, %2;" : "=r"(hp) : "f"(w1), "f"(w0));
    float r0 = w0 - __uint_as_float(hp << 16);
    float r1 = w1 - __uint_as_float(hp & 0xFFFF0000u);
    unsigned lp; asm("cvt.rn.bf16x2.f32 %0, %1, %2;" : "=r"(lp) : "f"(r1), "f"(r0));
    whi[i] = hp; wlo[i] = lp;
}

// ---------------------------------------------------------------------------
// Tensor-core ConvGRU conv (k5,p2), Cin=2C. CTA: 16x16 px tile x (NF*8) oc.
// 8 warps, warp = 2 tile-rows x all oc. mma m16n8k16, triple-pass hi/lo.
// A fragments: scalar LDS (conflict-free); B fragments: LDS.128 (permuted).
// ---------------------------------------------------------------------------
template<int MODE, int NF>
__global__ __launch_bounds__(256) void conv5_mma_kernel(
    const float* __restrict__ x, const float* __restrict__ srcB,
    const unsigned* __restrict__ whi, const unsigned* __restrict__ wlo,
    const float* __restrict__ bias,
    float* __restrict__ zbuf, float* __restrict__ hbuf, float* __restrict__ outbuf,
    int C, int H, int W)
{
    constexpr int OCW = NF * 8;
    constexpr int BP = OCW + 8, BCH = 5 * 8 * BP;
    constexpr int WCHUNKS = 160 * NF;          // 2hl * 40 tapq * (OCW/4)
    constexpr int WS = (WCHUNKS + 255) / 256;
    extern __shared__ char sm[];
    float*    s_f = (float*)sm;
    unsigned* s_a = (unsigned*)(sm + 25600);
    unsigned* s_b = (unsigned*)(sm + 25600 + 32000);
    const uint32_t sf0 = (uint32_t)__cvta_generic_to_shared(s_f);
    const uint32_t sb0 = (uint32_t)__cvta_generic_to_shared(s_b);

    const int Cout = (MODE == 0) ? 2 * C : C;
    const int nOcB = Cout / OCW;
    const int bx = blockIdx.x, by = blockIdx.y;
    const int ocB = blockIdx.z % nOcB, bb = blockIdx.z / nOcB;
    const int oc0 = ocB * OCW;
    const int tid = threadIdx.x;
    const int warp = tid >> 5, lane = tid & 31;
    const int g = lane >> 2, tig = lane & 3;
    const int wrow = warp * 2;
    const int hw = H * W;

    int t_g0, t_g1; bool t_v0, t_v1;
    {
        int r = tid / 20, c = tid - r * 20;
        int ih = by * 16 - 2 + r, iw = bx * 16 - 2 + c;
        t_v0 = ((unsigned)ih < (unsigned)H) && ((unsigned)iw < (unsigned)W);
        t_g0 = ih * W + iw;
        int p = tid + 256; r = p / 20; c = p - r * 20;
        ih = by * 16 - 2 + r; iw = bx * 16 - 2 + c;
        t_v1 = (p < 400) && ((unsigned)ih < (unsigned)H) && ((unsigned)iw < (unsigned)W);
        t_g1 = ih * W + iw;
    }
    int wsrc[WS]; uint32_t wdst[WS]; int whl[WS]; bool wact[WS];
    #pragma unroll
    for (int s = 0; s < WS; s++) {
        int j = tid + s * 256;
        wact[s] = j < WCHUNKS;
        if (!wact[s]) j = 0;
        int hl = j / (WCHUNKS / 2), r = j % (WCHUNKS / 2);
        int tap = r / (2 * NF * 8), r2 = r % (2 * NF * 8);
        int q = r2 / (2 * NF), c4 = r2 % (2 * NF);
        whl[s] = hl;
        wsrc[s] = (tap * 8 + q) * Cout + oc0 + c4 * 4;
        wdst[s] = (uint32_t)(hl * BCH + (tap * 8 + q) * BP + c4 * 4);
    }

    const float* xb  = x    + (long)bb * C * hw;
    const float* sbp = srcB + (long)bb * C * hw;
    const int nB = C >> 3;

    auto issueA = [&](int cb) {
        const float* base = (cb * 16 < C) ? (xb + (long)(cb * 16) * hw)
                                          : (sbp + (long)(cb * 16 - C) * hw);
        #pragma unroll
        for (int u = 0; u < 16; u++) {
            const float* bu = base + (long)u * hw;
            cp4(sf0 + (uint32_t)(u * 400 + tid) * 4, bu + (t_v0 ? t_g0 : 0), t_v0);
            if (tid < 144)
                cp4(sf0 + (uint32_t)(u * 400 + 256 + tid) * 4, bu + (t_v1 ? t_g1 : 0), t_v1);
        }
    };
    auto issueB = [&](int cb, int kh, int buf) {
        int off = (cb * 25 + kh * 5) * 8 * Cout;
        #pragma unroll
        for (int s = 0; s < WS; s++) {
            if (wact[s])
                cp16(sb0 + (uint32_t)(buf * 2 * BCH + wdst[s]) * 4,
                     (whl[s] ? wlo : whi) + off + wsrc[s]);
        }
    };

    float acc[2][NF][4];
    #pragma unroll
    for (int rp = 0; rp < 2; rp++)
        #pragma unroll
        for (int f = 0; f < NF; f++)
            #pragma unroll
            for (int e = 0; e < 4; e++) acc[rp][f][e] = 0.f;

    issueA(0); issueB(0, 0, 0); cp_commit();

    for (int cb = 0; cb < nB; cb++) {
        for (int kh = 0; kh < 5; kh++) {
            const int L = cb * 5 + kh, bbuf = L & 1;
            cp_wait<0>();
            __syncthreads();
            if (kh == 0) {
                for (int idx = tid; idx < 3200; idx += 256) {
                    int cp = idx / 400, px = idx - cp * 400;
                    float f0 = s_f[(2 * cp) * 400 + px];
                    float f1 = s_f[(2 * cp + 1) * 400 + px];
                    unsigned hp; asm("cvt.rn.bf16x2.f32 %0, %1, %2;" : "=r"(hp) : "f"(f1), "f"(f0));
                    float r0 = f0 - __uint_as_float(hp << 16);
                    float r1 = f1 - __uint_as_float(hp & 0xFFFF0000u);
                    unsigned lp; asm("cvt.rn.bf16x2.f32 %0, %1, %2;" : "=r"(lp) : "f"(r1), "f"(r0));
                    s_a[px * 20 + cp] = hp;
                    s_a[px * 20 + 8 + cp] = lp;
                }
                __syncthreads();
            }
            if (kh == 4) { if (cb + 1 < nB) issueB(cb + 1, 0, (L + 1) & 1); }
            else {
                issueB(cb, kh + 1, (L + 1) & 1);
                if (kh == 1 && cb + 1 < nB) issueA(cb + 1);
            }
            cp_commit();

            const unsigned* bh = s_b + bbuf * 2 * BCH;
            const unsigned* bl = bh + BCH;
            #pragma unroll
            for (int kw = 0; kw < 5; kw++) {
                const int rb = (kw * 8 + tig) * BP + g * 4;
                unsigned b0h[NF], b1h[NF], b0l[NF], b1l[NF];
                #pragma unroll
                for (int blk = 0; blk < NF / 4; blk++) {
                    *(uint4*)&b0h[blk*4] = *(const uint4*)&bh[rb + blk*32];
                    *(uint4*)&b1h[blk*4] = *(const uint4*)&bh[rb + blk*32 + 4*BP];
                    *(uint4*)&b0l[blk*4] = *(const uint4*)&bl[rb + blk*32];
                    *(uint4*)&b1l[blk*4] = *(const uint4*)&bl[rb + blk*32 + 4*BP];
                }
                #pragma unroll
                for (int rp = 0; rp < 2; rp++) {
                    const int pxb = (wrow + rp + kh) * 20 + kw;
                    const unsigned* a0 = s_a + (pxb + g) * 20 + tig;
                    const unsigned* a1 = s_a + (pxb + g + 8) * 20 + tig;
                    unsigned ah0 = a0[0], ah1 = a1[0], ah2 = a0[4], ah3 = a1[4];
                    unsigned al0 = a0[8], al1 = a1[8], al2 = a0[12], al3 = a1[12];
                    #pragma unroll
                    for (int f = 0; f < NF; f++) {
                        mma16816(acc[rp][f], ah0, ah1, ah2, ah3, b0h[f], b1h[f]);
                        mma16816(acc[rp][f], al0, al1, al2, al3, b0h[f], b1h[f]);
                        mma16816(acc[rp][f], ah0, ah1, ah2, ah3, b0l[f], b1l[f]);
                    }
                }
            }
        }
    }
    __syncthreads();

    const int row0 = by * 16 + wrow, colg = bx * 16 + g;
    #pragma unroll
    for (int rp = 0; rp < 2; rp++) {
        int row = row0 + rp;
        #pragma unroll
        for (int f = 0; f < NF; f++) {
            int ocx = oc0 + f * 8 + 2 * tig;
            float b0 = bias[ocx], b1 = bias[ocx + 1];
            float d0 = acc[rp][f][0], d1 = acc[rp][f][1];
            float d2 = acc[rp][f][2], d3 = acc[rp][f][3];
            if (MODE == 0) {
                if (ocx < C) {
                    long i0 = ((long)(bb * C + ocx)) * hw + row * W + colg;
                    long i1 = i0 + hw;
                    zbuf[i0]     = sigmoidf_(d0 + b0);
                    zbuf[i0 + 8] = sigmoidf_(d2 + b0);
                    zbuf[i1]     = sigmoidf_(d1 + b1);
                    zbuf[i1 + 8] = sigmoidf_(d3 + b1);
                } else {
                    long i0 = ((long)(bb * C + (ocx - C))) * hw + row * W + colg;
                    long i1 = i0 + hw;
                    outbuf[i0]     = sigmoidf_(d0 + b0) * hbuf[i0];
                    outbuf[i0 + 8] = sigmoidf_(d2 + b0) * hbuf[i0 + 8];
                    outbuf[i1]     = sigmoidf_(d1 + b1) * hbuf[i1];
                    outbuf[i1 + 8] = sigmoidf_(d3 + b1) * hbuf[i1 + 8];
                }
            } else {
                long i0 = ((long)(bb * C + ocx)) * hw + row * W + colg;
                long i1 = i0 + hw;
                float za = zbuf[i0], zb = zbuf[i0 + 8], zc = zbuf[i1], zd = zbuf[i1 + 8];
                float ha = hbuf[i0], hb = hbuf[i0 + 8], hc = hbuf[i1], hd = hbuf[i1 + 8];
                hbuf[i0]     = (1.f - za) * ha + za * tanhf(d0 + b0);
                hbuf[i0 + 8] = (1.f - zb) * hb + zb * tanhf(d2 + b0);
                hbuf[i1]     = (1.f - zc) * hc + zc * tanhf(d1 + b1);
                hbuf[i1 + 8] = (1.f - zd) * hd + zd * tanhf(d3 + b1);
            }
        }
    }
}

#define C5_SMEM4 (25600 + 32000 + 2*2*(5*8*40)*4)
#define C5_SMEM8 (25600 + 32000 + 2*2*(5*8*72)*4)

// ---------------------------------------------------------------------------
// fp32 strided conv k4s2p1 (c2/c3), proven R6 kernel.
// ---------------------------------------------------------------------------
template<int PX, int OCB>
__global__ __launch_bounds__((256/PX)*(OCB/8), 3) void conv4s2_kernel(
    const float* __restrict__ x, const float* __restrict__ wt,
    const float* __restrict__ bias, float* __restrict__ y,
    int Cin, int Cout, int Hin, int Win)
{
    constexpr int NPX = 256 / PX, NT = NPX * (OCB / 8);
    constexpr int TILE = 2448, TS = (TILE + NT - 1) / NT;
    constexpr int WW = 32 * OCB, WCH = WW / 4, WS = (WCH + NT - 1) / NT;
    constexpr int LD4 = (2 * PX + 2 + 3) / 4;

    const int Hout = Hin >> 1, Wout = Win >> 1;
    const int nOcB = Cout / OCB;
    const int bx = blockIdx.x, by = blockIdx.y;
    const int ocB = blockIdx.z % nOcB, bb = blockIdx.z / nOcB;
    const int oc0 = ocB * OCB;
    const int tid = threadIdx.x;
    const int pxg = tid % NPX, ocg = tid / NPX;
    const int ty = pxg / (16 / PX), x0 = (pxg % (16 / PX)) * PX;
    const int oh = by * 16 + ty, ow0 = bx * 16 + x0;
    const int ocb = oc0 + ocg * 8;
    const int hwin = Hin * Win;

    __shared__ float s_in[2][TILE];
    __shared__ float s_w[2][WW];
    const uint32_t sin0 = (uint32_t)__cvta_generic_to_shared(&s_in[0][0]);
    const uint32_t sw0  = (uint32_t)__cvta_generic_to_shared(&s_w[0][0]);

    int t_src[TS];
    #pragma unroll
    for (int s = 0; s < TS; s++) {
        int idx = tid + s * NT;
        int u = idx / 1224, pos = idx - u * 1224;
        int r = pos / 36, c = pos - r * 36;
        int ih = by * 32 - 1 + r, iw = bx * 32 - 1 + c;
        bool v = (idx < TILE) && (c < 34) && ((unsigned)ih < (unsigned)Hin) &&
                 ((unsigned)iw < (unsigned)Win);
        t_src[s] = v ? (u * hwin + ih * Win + iw) : -1;
    }
    int w_src[WS];
    #pragma unroll
    for (int s = 0; s < WS; s++) {
        int idx = tid + s * NT;
        bool act = idx < WCH;
        int u = idx / (16 * (OCB / 4)), rm = idx % (16 * (OCB / 4));
        int k = rm / (OCB / 4), c4 = rm % (OCB / 4);
        if (u > 1) u = 1;
        w_src[s] = act ? ((u * 16 + k) * Cout + oc0 + 4 * c4) : -1;
    }

    const float* xb = x + (long)bb * Cin * hwin;
    const int nB = Cin >> 1;

    auto issue = [&](int cb, int buf) {
        const float* base = xb + (long)(cb * 2) * hwin;
        #pragma unroll
        for (int s = 0; s < TS; s++) {
            if ((s + 1) * NT <= TILE || tid + s * NT < TILE) {
                int so = t_src[s];
                cp4(sin0 + (uint32_t)(buf * TILE + tid + s * NT) * 4,
                    base + (so < 0 ? 0 : so), so >= 0);
            }
        }
        const float* wb = wt + (size_t)cb * 32 * Cout;
        #pragma unroll
        for (int s = 0; s < WS; s++)
            if (w_src[s] >= 0)
                cp16(sw0 + (uint32_t)(buf * WW + (tid + s * NT) * 4) * 4, wb + w_src[s]);
        cp_commit();
    };

    ull acc[PX][4];
    #pragma unroll
    for (int p = 0; p < PX; p++)
        #pragma unroll
        for (int j = 0; j < 4; j++) acc[p][j] = 0ULL;

    issue(0, 0);
    for (int cb = 0; cb < nB; cb++) {
        const int buf = cb & 1;
        if (cb + 1 < nB) { issue(cb + 1, buf ^ 1); cp_wait<1>(); }
        else cp_wait<0>();
        __syncthreads();
        #pragma unroll
        for (int u = 0; u < 2; u++) {
            #pragma unroll
            for (int kh = 0; kh < 4; kh++) {
                const float4* rp = (const float4*)&s_in[buf][u * 1224 + (2 * ty + kh) * 36 + 2 * x0];
                float xr[4 * LD4];
                #pragma unroll
                for (int q = 0; q < LD4; q++) {
                    float4 t = rp[q];
                    xr[4*q] = t.x; xr[4*q+1] = t.y; xr[4*q+2] = t.z; xr[4*q+3] = t.w;
                }
                ull vx[2 * PX + 2];
                #pragma unroll
                for (int m = 0; m < 2 * PX + 2; m++) vx[m] = pack2(xr[m], xr[m]);
                #pragma unroll
                for (int kw = 0; kw < 4; kw++) {
                    const ulonglong2* wp = (const ulonglong2*)&s_w[buf][(u * 16 + kh * 4 + kw) * OCB + ocg * 8];
                    ulonglong2 wA = wp[0], wB = wp[1];
                    #pragma unroll
                    for (int p = 0; p < PX; p++) {
                        acc[p][0] = ffma2(wA.x, vx[kw + 2*p], acc[p][0]);
                        acc[p][1] = ffma2(wA.y, vx[kw + 2*p], acc[p][1]);
                        acc[p][2] = ffma2(wB.x, vx[kw + 2*p], acc[p][2]);
                        acc[p][3] = ffma2(wB.y, vx[kw + 2*p], acc[p][3]);
                    }
                }
            }
        }
        __syncthreads();
    }

    float val[8][PX];
    #pragma unroll
    for (int p = 0; p < PX; p++)
        #pragma unroll
        for (int jp = 0; jp < 4; jp++)
            unpack2(acc[p][jp], val[2*jp][p], val[2*jp+1][p]);

    const long hwout = (long)Hout * Wout;
    #pragma unroll
    for (int j = 0; j < 8; j++) {
        int oc = ocb + j;
        float b = bias[oc];
        #pragma unroll
        for (int q = 0; q < PX / 4; q++) {
            float4 o = make_float4(val[j][4*q+0] + b, val[j][4*q+1] + b,
                                   val[j][4*q+2] + b, val[j][4*q+3] + b);
            *(float4*)&y[((long)bb * Cout + oc) * hwout + (long)oh * Wout + ow0 + 4*q] = o;
        }
    }
}

__global__ __launch_bounds__(256) void conv4s2_c1_kernel(
    const float* __restrict__ x, long xbstride,
    const float* __restrict__ w, const float* __restrict__ bias,
    float* __restrict__ y, int Cout, int Hin, int Win)
{
    const int Hout = Hin >> 1, Wout = Win >> 1;
    const int nog = Cout >> 2;
    const int bx = blockIdx.x, by = blockIdx.y;
    const int ocg = blockIdx.z % nog, bb = blockIdx.z / nog;
    const int tx = threadIdx.x, ty = threadIdx.y;
    const int tid = ty * 16 + tx;
    const int oh = by * 16 + ty, ow = bx * 16 + tx;

    __shared__ float s_in[34 * 34];
    __shared__ float4 s_w4[16];

    float a0 = 0.f, a1 = 0.f, a2 = 0.f, a3 = 0.f;
    const int ih0 = by * 32 - 1, iw0 = bx * 32 - 1;
    const int oc0 = ocg * 4;
    const float* xc = x + (long)bb * xbstride;

    for (int i = tid; i < 34 * 34; i += 256) {
        int r = i / 34, c = i - r * 34;
        int ih = ih0 + r, iw = iw0 + c;
        float v = 0.f;
        if ((unsigned)ih < (unsigned)Hin && (unsigned)iw < (unsigned)Win)
            v = xc[ih * Win + iw];
        s_in[i] = v;
    }
    if (tid < 64) {
        int k = tid >> 2, j = tid & 3;
        ((float*)s_w4)[k * 4 + j] = w[(oc0 + j) * 16 + k];
    }
    __syncthreads();
    #pragma unroll
    for (int kh = 0; kh < 4; kh++)
        #pragma unroll
        for (int kw = 0; kw < 4; kw++) {
            float v = s_in[(2 * ty + kh) * 34 + 2 * tx + kw];
            float4 wv = s_w4[kh * 4 + kw];
            a0 += v * wv.x; a1 += v * wv.y; a2 += v * wv.z; a3 += v * wv.w;
        }
    const long cs = (long)Hout * Wout;
    long base = (((long)bb * Cout + oc0) * Hout + oh) * Wout + ow;
    y[base] = a0 + bias[oc0];           y[base + cs] = a1 + bias[oc0 + 1];
    y[base + 2 * cs] = a2 + bias[oc0 + 2]; y[base + 3 * cs] = a3 + bias[oc0 + 3];
}

__global__ void copyout_kernel(const float* __restrict__ a, int na,
                               const float* __restrict__ b, int nb,
                               const float* __restrict__ c, int nc,
                               float* __restrict__ out)
{
    int i = blockIdx.x * blockDim.x + threadIdx.x;
    if (i < na) out[i] = a[i];
    else if (i < na + nb) out[i] = b[i - na];
    else if (i < na + nb + nc) out[i] = c[i - na - nb];
}

extern "C" void kernel_launch(void* const* d_in, const int* in_sizes, int n_in,
                              void* d_out, int out_size)
{
    const float* input   = (const float*)d_in[0];
    const float* c1_w    = (const float*)d_in[1];
    const float* c1_b    = (const float*)d_in[2];
    const float* g1_zr_w = (const float*)d_in[3];
    const float* g1_zr_b = (const float*)d_in[4];
    const float* g1_h_w  = (const float*)d_in[5];
    const float* g1_h_b  = (const float*)d_in[6];
    const float* c2_w    = (const float*)d_in[7];
    const float* c2_b    = (const float*)d_in[8];
    const float* g2_zr_w = (const float*)d_in[9];
    const float* g2_zr_b = (const float*)d_in[10];
    const float* g2_h_w  = (const float*)d_in[11];
    const float* g2_h_b  = (const float*)d_in[12];
    const float* c3_w    = (const float*)d_in[13];
    const float* c3_b    = (const float*)d_in[14];
    const float* g3_zr_w = (const float*)d_in[15];
    const float* g3_zr_b = (const float*)d_in[16];
    const float* g3_h_w  = (const float*)d_in[17];
    const float* g3_h_b  = (const float*)d_in[18];

    float *h1, *x1, *z1, *rh1, *h2, *x2, *z2, *rh2, *h3, *x3, *z3, *rh3;
    cudaGetSymbolAddress((void**)&h1, g_h1);   cudaGetSymbolAddress((void**)&x1, g_x1);
    cudaGetSymbolAddress((void**)&z1, g_z1);   cudaGetSymbolAddress((void**)&rh1, g_rh1);
    cudaGetSymbolAddress((void**)&h2, g_h2);   cudaGetSymbolAddress((void**)&x2, g_x2);
    cudaGetSymbolAddress((void**)&z2, g_z2);   cudaGetSymbolAddress((void**)&rh2, g_rh2);
    cudaGetSymbolAddress((void**)&h3, g_h3);   cudaGetSymbolAddress((void**)&x3, g_x3);
    cudaGetSymbolAddress((void**)&z3, g_z3);   cudaGetSymbolAddress((void**)&rh3, g_rh3);

    float *wt_c2, *wt_c3;
    cudaGetSymbolAddress((void**)&wt_c2, g_wt_c2);
    cudaGetSymbolAddress((void**)&wt_c3, g_wt_c3);
    unsigned *whzr1,*wlzr1,*whh1,*wlh1,*whzr2,*wlzr2,*whh2,*wlh2,*whzr3,*wlzr3,*whh3,*wlh3;
    cudaGetSymbolAddress((void**)&whzr1, g_wh_zr1); cudaGetSymbolAddress((void**)&wlzr1, g_wl_zr1);
    cudaGetSymbolAddress((void**)&whh1,  g_wh_h1);  cudaGetSymbolAddress((void**)&wlh1,  g_wl_h1);
    cudaGetSymbolAddress((void**)&whzr2, g_wh_zr2); cudaGetSymbolAddress((void**)&wlzr2, g_wl_zr2);
    cudaGetSymbolAddress((void**)&whh2,  g_wh_h2);  cudaGetSymbolAddress((void**)&wlh2,  g_wl_h2);
    cudaGetSymbolAddress((void**)&whzr3, g_wh_zr3); cudaGetSymbolAddress((void**)&wlzr3, g_wl_zr3);
    cudaGetSymbolAddress((void**)&whh3,  g_wh_h3);  cudaGetSymbolAddress((void**)&wlh3,  g_wl_h3);

    cudaFuncSetAttribute(conv5_mma_kernel<0,8>, cudaFuncAttributeMaxDynamicSharedMemorySize, C5_SMEM8);
    cudaFuncSetAttribute(conv5_mma_kernel<0,4>, cudaFuncAttributeMaxDynamicSharedMemorySize, C5_SMEM4);
    cudaFuncSetAttribute(conv5_mma_kernel<1,4>, cudaFuncAttributeMaxDynamicSharedMemorySize, C5_SMEM4);

    cudaMemsetAsync(h1, 0, (size_t)S1_N * sizeof(float), 0);
    cudaMemsetAsync(h2, 0, (size_t)S2_N * sizeof(float), 0);
    cudaMemsetAsync(h3, 0, (size_t)S3_N * sizeof(float), 0);

    auto tr = [](const float* w, float* wt, int Cin, int K, int Cout) {
        int n = Cout * Cin * K;
        transpose_w_kernel<<<(n + 255) / 256, 256>>>(w, wt, Cin, K, Cout);
    };
    tr(c2_w, wt_c2, 64, 16, 128);
    tr(c3_w, wt_c3, 128, 16, 128);
    auto wp = [](const float* w, unsigned* wh, unsigned* wl, int Cin, int Cout) {
        int n = (Cin / 2) * 25 * Cout;
        wpack_kernel<<<(n + 255) / 256, 256>>>(w, wh, wl, Cin, Cout);
    };
    wp(g1_zr_w, whzr1, wlzr1, 128, 128);
    wp(g1_h_w,  whh1,  wlh1,  128, 64);
    wp(g2_zr_w, whzr2, wlzr2, 256, 256);
    wp(g2_h_w,  whh2,  wlh2,  256, 128);
    wp(g3_zr_w, whzr3, wlzr3, 256, 256);
    wp(g3_h_w,  whh3,  wlh3,  256, 128);

    const long in_bstride = (long)12 * 128 * 128;

    for (int t = 0; t < 12; t++) {
        // stage 1
        conv4s2_c1_kernel<<<dim3(4, 4, 8 * 16), dim3(16, 16)>>>(
            input + (long)t * 128 * 128, in_bstride, c1_w, c1_b, x1, 64, 128, 128);
        conv5_mma_kernel<0,8><<<dim3(4, 4, 8 * 2), 256, C5_SMEM8>>>(
            x1, h1, whzr1, wlzr1, g1_zr_b, z1, h1, rh1, 64, 64, 64);
        conv5_mma_kernel<1,4><<<dim3(4, 4, 8 * 2), 256, C5_SMEM4>>>(
            x1, rh1, whh1, wlh1, g1_h_b, z1, h1, nullptr, 64, 64, 64);
        // stage 2
        conv4s2_kernel<4, 16><<<dim3(2, 2, 8 * 8), 128>>>(
            h1, wt_c2, c2_b, x2, 64, 128, 64, 64);
        conv5_mma_kernel<0,8><<<dim3(2, 2, 8 * 4), 256, C5_SMEM8>>>(
            x2, h2, whzr2, wlzr2, g2_zr_b, z2, h2, rh2, 128, 32, 32);
        conv5_mma_kernel<1,4><<<dim3(2, 2, 8 * 4), 256, C5_SMEM4>>>(
            x2, rh2, whh2, wlh2, g2_h_b, z2, h2, nullptr, 128, 32, 32);
        // stage 3
        conv4s2_kernel<4, 16><<<dim3(1, 1, 8 * 8), 128>>>(
            h2, wt_c3, c3_b, x3, 128, 128, 32, 32);
        conv5_mma_kernel<0,4><<<dim3(1, 1, 8 * 8), 256, C5_SMEM4>>>(
            x3, h3, whzr3, wlzr3, g3_zr_b, z3, h3, rh3, 128, 16, 16);
        conv5_mma_kernel<1,4><<<dim3(1, 1, 8 * 4), 256, C5_SMEM4>>>(
            x3, rh3, whh3, wlh3, g3_h_b, z3, h3, nullptr, 128, 16, 16);
    }

    const int total = S1_N + S2_N + S3_N;
    copyout_kernel<<<(total + 255) / 256, 256>>>(h1, S1_N, h2, S2_N, h3, S3_N,
                                                 (float*)d_out);
}

// round 13
// speedup vs baseline: 1.2087x; 1.2087x over previous
#include <cuda_runtime.h>
#include <cuda_bf16.h>
#include <math.h>
#include <stdint.h>

#define S1_N (8*64*64*64)
#define S2_N (8*128*32*32)
#define S3_N (8*128*16*16)

__device__ float g_h1[S1_N], g_x1[S1_N], g_z1[S1_N], g_rh1[S1_N];
__device__ float g_h2[S2_N], g_x2[S2_N], g_z2[S2_N], g_rh2[S2_N];
__device__ float g_h3[S3_N], g_x3[S3_N], g_z3[S3_N], g_rh3[S3_N];

__device__ float g_wt_c2[64*16*128];
__device__ float g_wt_c3[128*16*128];

// bf16 hi/lo packed gate weights (identity layout):
// [( (cb*25+k)*8 + q )*Cout + oc], pair = (ch 2q, ch 2q+1)
__device__ unsigned g_wh_zr1[64*25*128],  g_wl_zr1[64*25*128];
__device__ unsigned g_wh_h1 [64*25*64],   g_wl_h1 [64*25*64];
__device__ unsigned g_wh_zr2[128*25*256], g_wl_zr2[128*25*256];
__device__ unsigned g_wh_h2 [128*25*128], g_wl_h2 [128*25*128];
__device__ unsigned g_wh_zr3[128*25*256], g_wl_zr3[128*25*256];
__device__ unsigned g_wh_h3 [128*25*128], g_wl_h3 [128*25*128];

typedef unsigned long long ull;

__device__ __forceinline__ ull pack2(float lo, float hi) {
    ull r; asm("mov.b64 %0, {%1, %2};" : "=l"(r) : "f"(lo), "f"(hi)); return r;
}
__device__ __forceinline__ void unpack2(ull v, float& lo, float& hi) {
    asm("mov.b64 {%0, %1}, %2;" : "=f"(lo), "=f"(hi) : "l"(v));
}
__device__ __forceinline__ ull ffma2(ull a, ull b, ull c) {
    ull d; asm("fma.rn.f32x2 %0, %1, %2, %3;" : "=l"(d) : "l"(a), "l"(b), "l"(c)); return d;
}
__device__ __forceinline__ float sigmoidf_(float v) { return 1.f / (1.f + expf(-v)); }

__device__ __forceinline__ void cp4(uint32_t dst, const float* src, bool p) {
    int sz = p ? 4 : 0;
    asm volatile("cp.async.ca.shared.global [%0], [%1], 4, %2;\n" :: "r"(dst), "l"(src), "r"(sz));
}
__device__ __forceinline__ void cp16(uint32_t dst, const void* src) {
    asm volatile("cp.async.cg.shared.global [%0], [%1], 16;\n" :: "r"(dst), "l"(src));
}
__device__ __forceinline__ void cp_commit() { asm volatile("cp.async.commit_group;\n"); }
template<int N> __device__ __forceinline__ void cp_wait() {
    asm volatile("cp.async.wait_group %0;\n" :: "n"(N));
}
__device__ __forceinline__ void mma16816(float* d, unsigned a0, unsigned a1,
                                         unsigned a2, unsigned a3, unsigned b0, unsigned b1) {
    asm("mma.sync.aligned.m16n8k16.row.col.f32.bf16.bf16.f32 "
        "{%0,%1,%2,%3}, {%4,%5,%6,%7}, {%8,%9}, {%0,%1,%2,%3};"
        : "+f"(d[0]), "+f"(d[1]), "+f"(d[2]), "+f"(d[3])
        : "r"(a0), "r"(a1), "r"(a2), "r"(a3), "r"(b0), "r"(b1));
}

__global__ void transpose_w_kernel(const float* __restrict__ w, float* __restrict__ wt,
                                   int Cin, int K, int Cout)
{
    int i = blockIdx.x * blockDim.x + threadIdx.x;
    if (i >= Cout * Cin * K) return;
    int oc = i / (Cin * K);
    int rem = i - oc * (Cin * K);
    int ci = rem / K, k = rem - (rem / K) * K;
    wt[(ci * K + k) * Cout + oc] = w[i];
}

// identity pack (R9-proven)
__global__ void wpack_kernel(const float* __restrict__ w, unsigned* __restrict__ whi,
                             unsigned* __restrict__ wlo, int Cin, int Cout)
{
    int i = blockIdx.x * blockDim.x + threadIdx.x;
    if (i >= (Cin / 2) * 25 * Cout) return;
    int oc = i % Cout;
    int pr = i / Cout;
    int cb = pr / 200, r2 = pr - cb * 200;
    int k = r2 >> 3, q = r2 & 7;
    int ch0 = cb * 16 + 2 * q;
    float w0 = w[(oc * Cin + ch0) * 25 + k];
    float w1 = w[(oc * Cin + ch0 + 1) * 25 + k];
    unsigned hp; asm("cvt.rn.bf16x2.f32 %0, %1, %2;" : "=r"(hp) : "f"(w1), "f"(w0));
    float r0 = w0 - __uint_as_float(hp << 16);
    float r1 = w1 - __uint_as_float(hp & 0xFFFF0000u);
    unsigned lp; asm("cvt.rn.bf16x2.f32 %0, %1, %2;" : "=r"(lp) : "f"(r1), "f"(r0));
    whi[i] = hp; wlo[i] = lp;
}

// ---------------------------------------------------------------------------
// Tensor-core ConvGRU conv (k5,p2), Cin=2C. CTA: 16x16 px tile x (NF*8) oc.
// 8 warps, warp = 2 tile-rows x all oc. mma m16n8k16, triple-pass hi/lo.
// Scalar conflict-free LDS for A and B (R9-proven configuration).
// ---------------------------------------------------------------------------
template<int MODE, int NF>
__global__ __launch_bounds__(256) void conv5_mma_kernel(
    const float* __restrict__ x, const float* __restrict__ srcB,
    const unsigned* __restrict__ whi, const unsigned* __restrict__ wlo,
    const float* __restrict__ bias,
    float* __restrict__ zbuf, float* __restrict__ hbuf, float* __restrict__ outbuf,
    int C, int H, int W)
{
    constexpr int OCW = NF * 8;
    constexpr int BP = OCW + 8, BCH = 5 * 8 * BP;
    constexpr int WCHUNKS = 160 * NF;
    constexpr int WS = (WCHUNKS + 255) / 256;
    extern __shared__ char sm[];
    float*    s_f = (float*)sm;
    unsigned* s_a = (unsigned*)(sm + 25600);
    unsigned* s_b = (unsigned*)(sm + 25600 + 32000);
    const uint32_t sf0 = (uint32_t)__cvta_generic_to_shared(s_f);
    const uint32_t sb0 = (uint32_t)__cvta_generic_to_shared(s_b);

    const int Cout = (MODE == 0) ? 2 * C : C;
    const int nOcB = Cout / OCW;
    const int bx = blockIdx.x, by = blockIdx.y;
    const int ocB = blockIdx.z % nOcB, bb = blockIdx.z / nOcB;
    const int oc0 = ocB * OCW;
    const int tid = threadIdx.x;
    const int warp = tid >> 5, lane = tid & 31;
    const int g = lane >> 2, tig = lane & 3;
    const int wrow = warp * 2;
    const int hw = H * W;

    int t_g0, t_g1; bool t_v0, t_v1;
    {
        int r = tid / 20, c = tid - r * 20;
        int ih = by * 16 - 2 + r, iw = bx * 16 - 2 + c;
        t_v0 = ((unsigned)ih < (unsigned)H) && ((unsigned)iw < (unsigned)W);
        t_g0 = ih * W + iw;
        int p = tid + 256; r = p / 20; c = p - r * 20;
        ih = by * 16 - 2 + r; iw = bx * 16 - 2 + c;
        t_v1 = (p < 400) && ((unsigned)ih < (unsigned)H) && ((unsigned)iw < (unsigned)W);
        t_g1 = ih * W + iw;
    }
    int wsrc[WS]; uint32_t wdst[WS]; int whl[WS]; bool wact[WS];
    #pragma unroll
    for (int s = 0; s < WS; s++) {
        int j = tid + s * 256;
        wact[s] = j < WCHUNKS;
        if (!wact[s]) j = 0;
        int hl = j / (WCHUNKS / 2), r = j % (WCHUNKS / 2);
        int tap = r / (2 * NF * 8), r2 = r % (2 * NF * 8);
        int q = r2 / (2 * NF), c4 = r2 % (2 * NF);
        whl[s] = hl;
        wsrc[s] = (tap * 8 + q) * Cout + oc0 + c4 * 4;
        wdst[s] = (uint32_t)(hl * BCH + (tap * 8 + q) * BP + c4 * 4);
    }

    const float* xb  = x    + (long)bb * C * hw;
    const float* sbp = srcB + (long)bb * C * hw;
    const int nB = C >> 3;

    auto issueA = [&](int cb) {
        const float* base = (cb * 16 < C) ? (xb + (long)(cb * 16) * hw)
                                          : (sbp + (long)(cb * 16 - C) * hw);
        #pragma unroll
        for (int u = 0; u < 16; u++) {
            const float* bu = base + (long)u * hw;
            cp4(sf0 + (uint32_t)(u * 400 + tid) * 4, bu + (t_v0 ? t_g0 : 0), t_v0);
            if (tid < 144)
                cp4(sf0 + (uint32_t)(u * 400 + 256 + tid) * 4, bu + (t_v1 ? t_g1 : 0), t_v1);
        }
    };
    auto issueB = [&](int cb, int kh, int buf) {
        int off = (cb * 25 + kh * 5) * 8 * Cout;
        #pragma unroll
        for (int s = 0; s < WS; s++) {
            if (wact[s])
                cp16(sb0 + (uint32_t)(buf * 2 * BCH + wdst[s]) * 4,
                     (whl[s] ? wlo : whi) + off + wsrc[s]);
        }
    };

    float acc[2][NF][4];
    #pragma unroll
    for (int rp = 0; rp < 2; rp++)
        #pragma unroll
        for (int f = 0; f < NF; f++)
            #pragma unroll
            for (int e = 0; e < 4; e++) acc[rp][f][e] = 0.f;

    issueA(0); issueB(0, 0, 0); cp_commit();

    for (int cb = 0; cb < nB; cb++) {
        for (int kh = 0; kh < 5; kh++) {
            const int L = cb * 5 + kh, bbuf = L & 1;
            cp_wait<0>();
            __syncthreads();
            if (kh == 0) {
                for (int idx = tid; idx < 3200; idx += 256) {
                    int cp = idx / 400, px = idx - cp * 400;
                    float f0 = s_f[(2 * cp) * 400 + px];
                    float f1 = s_f[(2 * cp + 1) * 400 + px];
                    unsigned hp; asm("cvt.rn.bf16x2.f32 %0, %1, %2;" : "=r"(hp) : "f"(f1), "f"(f0));
                    float r0 = f0 - __uint_as_float(hp << 16);
                    float r1 = f1 - __uint_as_float(hp & 0xFFFF0000u);
                    unsigned lp; asm("cvt.rn.bf16x2.f32 %0, %1, %2;" : "=r"(lp) : "f"(r1), "f"(r0));
                    s_a[px * 20 + cp] = hp;
                    s_a[px * 20 + 8 + cp] = lp;
                }
                __syncthreads();
            }
            if (kh == 4) { if (cb + 1 < nB) issueB(cb + 1, 0, (L + 1) & 1); }
            else {
                issueB(cb, kh + 1, (L + 1) & 1);
                if (kh == 1 && cb + 1 < nB) issueA(cb + 1);
            }
            cp_commit();

            const unsigned* bh = s_b + bbuf * 2 * BCH;
            const unsigned* bl = bh + BCH;
            #pragma unroll
            for (int kw = 0; kw < 5; kw++) {
                unsigned b0h[NF], b1h[NF], b0l[NF], b1l[NF];
                const int br = (kw * 8 + tig) * BP + g;
                #pragma unroll
                for (int f = 0; f < NF; f++) {
                    b0h[f] = bh[br + f * 8]; b1h[f] = bh[br + 4 * BP + f * 8];
                    b0l[f] = bl[br + f * 8]; b1l[f] = bl[br + 4 * BP + f * 8];
                }
                #pragma unroll
                for (int rp = 0; rp < 2; rp++) {
                    const int pxb = (wrow + rp + kh) * 20 + kw;
                    const unsigned* a0 = s_a + (pxb + g) * 20 + tig;
                    const unsigned* a1 = s_a + (pxb + g + 8) * 20 + tig;
                    unsigned ah0 = a0[0], ah1 = a1[0], ah2 = a0[4], ah3 = a1[4];
                    unsigned al0 = a0[8], al1 = a1[8], al2 = a0[12], al3 = a1[12];
                    #pragma unroll
                    for (int f = 0; f < NF; f++) {
                        mma16816(acc[rp][f], ah0, ah1, ah2, ah3, b0h[f], b1h[f]);
                        mma16816(acc[rp][f], al0, al1, al2, al3, b0h[f], b1h[f]);
                        mma16816(acc[rp][f], ah0, ah1, ah2, ah3, b0l[f], b1l[f]);
                    }
                }
            }
        }
    }
    __syncthreads();

    const int row0 = by * 16 + wrow, colg = bx * 16 + g;
    #pragma unroll
    for (int rp = 0; rp < 2; rp++) {
        int row = row0 + rp;
        #pragma unroll
        for (int f = 0; f < NF; f++) {
            int ocx = oc0 + f * 8 + 2 * tig;
            float b0 = bias[ocx], b1 = bias[ocx + 1];
            float d0 = acc[rp][f][0], d1 = acc[rp][f][1];
            float d2 = acc[rp][f][2], d3 = acc[rp][f][3];
            if (MODE == 0) {
                if (ocx < C) {
                    long i0 = ((long)(bb * C + ocx)) * hw + row * W + colg;
                    long i1 = i0 + hw;
                    zbuf[i0]     = sigmoidf_(d0 + b0);
                    zbuf[i0 + 8] = sigmoidf_(d2 + b0);
                    zbuf[i1]     = sigmoidf_(d1 + b1);
                    zbuf[i1 + 8] = sigmoidf_(d3 + b1);
                } else {
                    long i0 = ((long)(bb * C + (ocx - C))) * hw + row * W + colg;
                    long i1 = i0 + hw;
                    outbuf[i0]     = sigmoidf_(d0 + b0) * hbuf[i0];
                    outbuf[i0 + 8] = sigmoidf_(d2 + b0) * hbuf[i0 + 8];
                    outbuf[i1]     = sigmoidf_(d1 + b1) * hbuf[i1];
                    outbuf[i1 + 8] = sigmoidf_(d3 + b1) * hbuf[i1 + 8];
                }
            } else {
                long i0 = ((long)(bb * C + ocx)) * hw + row * W + colg;
                long i1 = i0 + hw;
                float za = zbuf[i0], zb = zbuf[i0 + 8], zc = zbuf[i1], zd = zbuf[i1 + 8];
                float ha = hbuf[i0], hb = hbuf[i0 + 8], hc = hbuf[i1], hd = hbuf[i1 + 8];
                hbuf[i0]     = (1.f - za) * ha + za * tanhf(d0 + b0);
                hbuf[i0 + 8] = (1.f - zb) * hb + zb * tanhf(d2 + b0);
                hbuf[i1]     = (1.f - zc) * hc + zc * tanhf(d1 + b1);
                hbuf[i1 + 8] = (1.f - zd) * hd + zd * tanhf(d3 + b1);
            }
        }
    }
}

#define C5_SMEM(NF) (25600 + 32000 + 2*2*(5*8*((NF)*8+8))*4)

// ---------------------------------------------------------------------------
// fp32 strided conv k4s2p1 (c2/c3), proven R6 kernel.
// ---------------------------------------------------------------------------
template<int PX, int OCB>
__global__ __launch_bounds__((256/PX)*(OCB/8), 3) void conv4s2_kernel(
    const float* __restrict__ x, const float* __restrict__ wt,
    const float* __restrict__ bias, float* __restrict__ y,
    int Cin, int Cout, int Hin, int Win)
{
    constexpr int NPX = 256 / PX, NT = NPX * (OCB / 8);
    constexpr int TILE = 2448, TS = (TILE + NT - 1) / NT;
    constexpr int WW = 32 * OCB, WCH = WW / 4, WS = (WCH + NT - 1) / NT;
    constexpr int LD4 = (2 * PX + 2 + 3) / 4;

    const int Hout = Hin >> 1, Wout = Win >> 1;
    const int nOcB = Cout / OCB;
    const int bx = blockIdx.x, by = blockIdx.y;
    const int ocB = blockIdx.z % nOcB, bb = blockIdx.z / nOcB;
    const int oc0 = ocB * OCB;
    const int tid = threadIdx.x;
    const int pxg = tid % NPX, ocg = tid / NPX;
    const int ty = pxg / (16 / PX), x0 = (pxg % (16 / PX)) * PX;
    const int oh = by * 16 + ty, ow0 = bx * 16 + x0;
    const int ocb = oc0 + ocg * 8;
    const int hwin = Hin * Win;

    __shared__ float s_in[2][TILE];
    __shared__ float s_w[2][WW];
    const uint32_t sin0 = (uint32_t)__cvta_generic_to_shared(&s_in[0][0]);
    const uint32_t sw0  = (uint32_t)__cvta_generic_to_shared(&s_w[0][0]);

    int t_src[TS];
    #pragma unroll
    for (int s = 0; s < TS; s++) {
        int idx = tid + s * NT;
        int u = idx / 1224, pos = idx - u * 1224;
        int r = pos / 36, c = pos - r * 36;
        int ih = by * 32 - 1 + r, iw = bx * 32 - 1 + c;
        bool v = (idx < TILE) && (c < 34) && ((unsigned)ih < (unsigned)Hin) &&
                 ((unsigned)iw < (unsigned)Win);
        t_src[s] = v ? (u * hwin + ih * Win + iw) : -1;
    }
    int w_src[WS];
    #pragma unroll
    for (int s = 0; s < WS; s++) {
        int idx = tid + s * NT;
        bool act = idx < WCH;
        int u = idx / (16 * (OCB / 4)), rm = idx % (16 * (OCB / 4));
        int k = rm / (OCB / 4), c4 = rm % (OCB / 4);
        if (u > 1) u = 1;
        w_src[s] = act ? ((u * 16 + k) * Cout + oc0 + 4 * c4) : -1;
    }

    const float* xb = x + (long)bb * Cin * hwin;
    const int nB = Cin >> 1;

    auto issue = [&](int cb, int buf) {
        const float* base = xb + (long)(cb * 2) * hwin;
        #pragma unroll
        for (int s = 0; s < TS; s++) {
            if ((s + 1) * NT <= TILE || tid + s * NT < TILE) {
                int so = t_src[s];
                cp4(sin0 + (uint32_t)(buf * TILE + tid + s * NT) * 4,
                    base + (so < 0 ? 0 : so), so >= 0);
            }
        }
        const float* wb = wt + (size_t)cb * 32 * Cout;
        #pragma unroll
        for (int s = 0; s < WS; s++)
            if (w_src[s] >= 0)
                cp16(sw0 + (uint32_t)(buf * WW + (tid + s * NT) * 4) * 4, wb + w_src[s]);
        cp_commit();
    };

    ull acc[PX][4];
    #pragma unroll
    for (int p = 0; p < PX; p++)
        #pragma unroll
        for (int j = 0; j < 4; j++) acc[p][j] = 0ULL;

    issue(0, 0);
    for (int cb = 0; cb < nB; cb++) {
        const int buf = cb & 1;
        if (cb + 1 < nB) { issue(cb + 1, buf ^ 1); cp_wait<1>(); }
        else cp_wait<0>();
        __syncthreads();
        #pragma unroll
        for (int u = 0; u < 2; u++) {
            #pragma unroll
            for (int kh = 0; kh < 4; kh++) {
                const float4* rp = (const float4*)&s_in[buf][u * 1224 + (2 * ty + kh) * 36 + 2 * x0];
                float xr[4 * LD4];
                #pragma unroll
                for (int q = 0; q < LD4; q++) {
                    float4 t = rp[q];
                    xr[4*q] = t.x; xr[4*q+1] = t.y; xr[4*q+2] = t.z; xr[4*q+3] = t.w;
                }
                ull vx[2 * PX + 2];
                #pragma unroll
                for (int m = 0; m < 2 * PX + 2; m++) vx[m] = pack2(xr[m], xr[m]);
                #pragma unroll
                for (int kw = 0; kw < 4; kw++) {
                    const ulonglong2* wp = (const ulonglong2*)&s_w[buf][(u * 16 + kh * 4 + kw) * OCB + ocg * 8];
                    ulonglong2 wA = wp[0], wB = wp[1];
                    #pragma unroll
                    for (int p = 0; p < PX; p++) {
                        acc[p][0] = ffma2(wA.x, vx[kw + 2*p], acc[p][0]);
                        acc[p][1] = ffma2(wA.y, vx[kw + 2*p], acc[p][1]);
                        acc[p][2] = ffma2(wB.x, vx[kw + 2*p], acc[p][2]);
                        acc[p][3] = ffma2(wB.y, vx[kw + 2*p], acc[p][3]);
                    }
                }
            }
        }
        __syncthreads();
    }

    float val[8][PX];
    #pragma unroll
    for (int p = 0; p < PX; p++)
        #pragma unroll
        for (int jp = 0; jp < 4; jp++)
            unpack2(acc[p][jp], val[2*jp][p], val[2*jp+1][p]);

    const long hwout = (long)Hout * Wout;
    #pragma unroll
    for (int j = 0; j < 8; j++) {
        int oc = ocb + j;
        float b = bias[oc];
        #pragma unroll
        for (int q = 0; q < PX / 4; q++) {
            float4 o = make_float4(val[j][4*q+0] + b, val[j][4*q+1] + b,
                                   val[j][4*q+2] + b, val[j][4*q+3] + b);
            *(float4*)&y[((long)bb * Cout + oc) * hwout + (long)oh * Wout + ow0 + 4*q] = o;
        }
    }
}

__global__ __launch_bounds__(256) void conv4s2_c1_kernel(
    const float* __restrict__ x, long xbstride,
    const float* __restrict__ w, const float* __restrict__ bias,
    float* __restrict__ y, int Cout, int Hin, int Win)
{
    const int Hout = Hin >> 1, Wout = Win >> 1;
    const int nog = Cout >> 2;
    const int bx = blockIdx.x, by = blockIdx.y;
    const int ocg = blockIdx.z % nog, bb = blockIdx.z / nog;
    const int tx = threadIdx.x, ty = threadIdx.y;
    const int tid = ty * 16 + tx;
    const int oh = by * 16 + ty, ow = bx * 16 + tx;

    __shared__ float s_in[34 * 34];
    __shared__ float4 s_w4[16];

    float a0 = 0.f, a1 = 0.f, a2 = 0.f, a3 = 0.f;
    const int ih0 = by * 32 - 1, iw0 = bx * 32 - 1;
    const int oc0 = ocg * 4;
    const float* xc = x + (long)bb * xbstride;

    for (int i = tid; i < 34 * 34; i += 256) {
        int r = i / 34, c = i - r * 34;
        int ih = ih0 + r, iw = iw0 + c;
        float v = 0.f;
        if ((unsigned)ih < (unsigned)Hin && (unsigned)iw < (unsigned)Win)
            v = xc[ih * Win + iw];
        s_in[i] = v;
    }
    if (tid < 64) {
        int k = tid >> 2, j = tid & 3;
        ((float*)s_w4)[k * 4 + j] = w[(oc0 + j) * 16 + k];
    }
    __syncthreads();
    #pragma unroll
    for (int kh = 0; kh < 4; kh++)
        #pragma unroll
        for (int kw = 0; kw < 4; kw++) {
            float v = s_in[(2 * ty + kh) * 34 + 2 * tx + kw];
            float4 wv = s_w4[kh * 4 + kw];
            a0 += v * wv.x; a1 += v * wv.y; a2 += v * wv.z; a3 += v * wv.w;
        }
    const long cs = (long)Hout * Wout;
    long base = (((long)bb * Cout + oc0) * Hout + oh) * Wout + ow;
    y[base] = a0 + bias[oc0];           y[base + cs] = a1 + bias[oc0 + 1];
    y[base + 2 * cs] = a2 + bias[oc0 + 2]; y[base + 3 * cs] = a3 + bias[oc0 + 3];
}

__global__ void copyout_kernel(const float* __restrict__ a, int na,
                               const float* __restrict__ b, int nb,
                               const float* __restrict__ c, int nc,
                               float* __restrict__ out)
{
    int i = blockIdx.x * blockDim.x + threadIdx.x;
    if (i < na) out[i] = a[i];
    else if (i < na + nb) out[i] = b[i - na];
    else if (i < na + nb + nc) out[i] = c[i - na - nb];
}

extern "C" void kernel_launch(void* const* d_in, const int* in_sizes, int n_in,
                              void* d_out, int out_size)
{
    const float* input   = (const float*)d_in[0];
    const float* c1_w    = (const float*)d_in[1];
    const float* c1_b    = (const float*)d_in[2];
    const float* g1_zr_w = (const float*)d_in[3];
    const float* g1_zr_b = (const float*)d_in[4];
    const float* g1_h_w  = (const float*)d_in[5];
    const float* g1_h_b  = (const float*)d_in[6];
    const float* c2_w    = (const float*)d_in[7];
    const float* c2_b    = (const float*)d_in[8];
    const float* g2_zr_w = (const float*)d_in[9];
    const float* g2_zr_b = (const float*)d_in[10];
    const float* g2_h_w  = (const float*)d_in[11];
    const float* g2_h_b  = (const float*)d_in[12];
    const float* c3_w    = (const float*)d_in[13];
    const float* c3_b    = (const float*)d_in[14];
    const float* g3_zr_w = (const float*)d_in[15];
    const float* g3_zr_b = (const float*)d_in[16];
    const float* g3_h_w  = (const float*)d_in[17];
    const float* g3_h_b  = (const float*)d_in[18];

    float *h1, *x1, *z1, *rh1, *h2, *x2, *z2, *rh2, *h3, *x3, *z3, *rh3;
    cudaGetSymbolAddress((void**)&h1, g_h1);   cudaGetSymbolAddress((void**)&x1, g_x1);
    cudaGetSymbolAddress((void**)&z1, g_z1);   cudaGetSymbolAddress((void**)&rh1, g_rh1);
    cudaGetSymbolAddress((void**)&h2, g_h2);   cudaGetSymbolAddress((void**)&x2, g_x2);
    cudaGetSymbolAddress((void**)&z2, g_z2);   cudaGetSymbolAddress((void**)&rh2, g_rh2);
    cudaGetSymbolAddress((void**)&h3, g_h3);   cudaGetSymbolAddress((void**)&x3, g_x3);
    cudaGetSymbolAddress((void**)&z3, g_z3);   cudaGetSymbolAddress((void**)&rh3, g_rh3);

    float *wt_c2, *wt_c3;
    cudaGetSymbolAddress((void**)&wt_c2, g_wt_c2);
    cudaGetSymbolAddress((void**)&wt_c3, g_wt_c3);
    unsigned *whzr1,*wlzr1,*whh1,*wlh1,*whzr2,*wlzr2,*whh2,*wlh2,*whzr3,*wlzr3,*whh3,*wlh3;
    cudaGetSymbolAddress((void**)&whzr1, g_wh_zr1); cudaGetSymbolAddress((void**)&wlzr1, g_wl_zr1);
    cudaGetSymbolAddress((void**)&whh1,  g_wh_h1);  cudaGetSymbolAddress((void**)&wlh1,  g_wl_h1);
    cudaGetSymbolAddress((void**)&whzr2, g_wh_zr2); cudaGetSymbolAddress((void**)&wlzr2, g_wl_zr2);
    cudaGetSymbolAddress((void**)&whh2,  g_wh_h2);  cudaGetSymbolAddress((void**)&wlh2,  g_wl_h2);
    cudaGetSymbolAddress((void**)&whzr3, g_wh_zr3); cudaGetSymbolAddress((void**)&wlzr3, g_wl_zr3);
    cudaGetSymbolAddress((void**)&whh3,  g_wh_h3);  cudaGetSymbolAddress((void**)&wlh3,  g_wl_h3);

    cudaFuncSetAttribute(conv5_mma_kernel<0,4>, cudaFuncAttributeMaxDynamicSharedMemorySize, C5_SMEM(4));
    cudaFuncSetAttribute(conv5_mma_kernel<1,4>, cudaFuncAttributeMaxDynamicSharedMemorySize, C5_SMEM(4));
    cudaFuncSetAttribute(conv5_mma_kernel<0,2>, cudaFuncAttributeMaxDynamicSharedMemorySize, C5_SMEM(2));
    cudaFuncSetAttribute(conv5_mma_kernel<1,2>, cudaFuncAttributeMaxDynamicSharedMemorySize, C5_SMEM(2));

    cudaMemsetAsync(h1, 0, (size_t)S1_N * sizeof(float), 0);
    cudaMemsetAsync(h2, 0, (size_t)S2_N * sizeof(float), 0);
    cudaMemsetAsync(h3, 0, (size_t)S3_N * sizeof(float), 0);

    auto tr = [](const float* w, float* wt, int Cin, int K, int Cout) {
        int n = Cout * Cin * K;
        transpose_w_kernel<<<(n + 255) / 256, 256>>>(w, wt, Cin, K, Cout);
    };
    tr(c2_w, wt_c2, 64, 16, 128);
    tr(c3_w, wt_c3, 128, 16, 128);
    auto wp = [](const float* w, unsigned* wh, unsigned* wl, int Cin, int Cout) {
        int n = (Cin / 2) * 25 * Cout;
        wpack_kernel<<<(n + 255) / 256, 256>>>(w, wh, wl, Cin, Cout);
    };
    wp(g1_zr_w, whzr1, wlzr1, 128, 128);
    wp(g1_h_w,  whh1,  wlh1,  128, 64);
    wp(g2_zr_w, whzr2, wlzr2, 256, 256);
    wp(g2_h_w,  whh2,  wlh2,  256, 128);
    wp(g3_zr_w, whzr3, wlzr3, 256, 256);
    wp(g3_h_w,  whh3,  wlh3,  256, 128);

    const long in_bstride = (long)12 * 128 * 128;

    for (int t = 0; t < 12; t++) {
        // stage 1
        conv4s2_c1_kernel<<<dim3(4, 4, 8 * 16), dim3(16, 16)>>>(
            input + (long)t * 128 * 128, in_bstride, c1_w, c1_b, x1, 64, 128, 128);
        conv5_mma_kernel<0,4><<<dim3(4, 4, 8 * 4), 256, C5_SMEM(4)>>>(
            x1, h1, whzr1, wlzr1, g1_zr_b, z1, h1, rh1, 64, 64, 64);
        conv5_mma_kernel<1,4><<<dim3(4, 4, 8 * 2), 256, C5_SMEM(4)>>>(
            x1, rh1, whh1, wlh1, g1_h_b, z1, h1, nullptr, 64, 64, 64);
        // stage 2
        conv4s2_kernel<4, 16><<<dim3(2, 2, 8 * 8), 128>>>(
            h1, wt_c2, c2_b, x2, 64, 128, 64, 64);
        conv5_mma_kernel<0,4><<<dim3(2, 2, 8 * 8), 256, C5_SMEM(4)>>>(
            x2, h2, whzr2, wlzr2, g2_zr_b, z2, h2, rh2, 128, 32, 32);
        conv5_mma_kernel<1,4><<<dim3(2, 2, 8 * 4), 256, C5_SMEM(4)>>>(
            x2, rh2, whh2, wlh2, g2_h_b, z2, h2, nullptr, 128, 32, 32);
        // stage 3 (NF=2: 2x grid, 3 CTAs/SM)
        conv4s2_kernel<4, 16><<<dim3(1, 1, 8 * 8), 128>>>(
            h2, wt_c3, c3_b, x3, 128, 128, 32, 32);
        conv5_mma_kernel<0,2><<<dim3(1, 1, 8 * 16), 256, C5_SMEM(2)>>>(
            x3, h3, whzr3, wlzr3, g3_zr_b, z3, h3, rh3, 128, 16, 16);
        conv5_mma_kernel<1,2><<<dim3(1, 1, 8 * 8), 256, C5_SMEM(2)>>>(
            x3, rh3, whh3, wlh3, g3_h_b, z3, h3, nullptr, 128, 16, 16);
    }

    const int total = S1_N + S2_N + S3_N;
    copyout_kernel<<<(total + 255) / 256, 256>>>(h1, S1_N, h2, S2_N, h3, S3_N,
                                                 (float*)d_out);
}

// round 14
// speedup vs baseline: 1.5245x; 1.2613x over previous
#include <cuda_runtime.h>
#include <cuda_bf16.h>
#include <math.h>
#include <stdint.h>

#define S1_N (8*64*64*64)
#define S2_N (8*128*32*32)
#define S3_N (8*128*16*16)

__device__ float g_h1[S1_N], g_x1[S1_N], g_z1[S1_N], g_rh1[S1_N];
__device__ float g_h2[S2_N], g_x2[S2_N], g_z2[S2_N], g_rh2[S2_N];
__device__ float g_h3[S3_N], g_x3[S3_N], g_z3[S3_N], g_rh3[S3_N];

__device__ float g_wt_c2[64*16*128];
__device__ float g_wt_c3[128*16*128];

// bf16 hi/lo packed gate weights (identity layout):
// [( (cb*25+k)*8 + q )*Cout + oc], pair = (ch 2q, ch 2q+1)
__device__ unsigned g_wh_zr1[64*25*128],  g_wl_zr1[64*25*128];
__device__ unsigned g_wh_h1 [64*25*64],   g_wl_h1 [64*25*64];
__device__ unsigned g_wh_zr2[128*25*256], g_wl_zr2[128*25*256];
__device__ unsigned g_wh_h2 [128*25*128], g_wl_h2 [128*25*128];
__device__ unsigned g_wh_zr3[128*25*256], g_wl_zr3[128*25*256];
__device__ unsigned g_wh_h3 [128*25*128], g_wl_h3 [128*25*128];

typedef unsigned long long ull;

__device__ __forceinline__ ull pack2(float lo, float hi) {
    ull r; asm("mov.b64 %0, {%1, %2};" : "=l"(r) : "f"(lo), "f"(hi)); return r;
}
__device__ __forceinline__ void unpack2(ull v, float& lo, float& hi) {
    asm("mov.b64 {%0, %1}, %2;" : "=f"(lo), "=f"(hi) : "l"(v));
}
__device__ __forceinline__ ull ffma2(ull a, ull b, ull c) {
    ull d; asm("fma.rn.f32x2 %0, %1, %2, %3;" : "=l"(d) : "l"(a), "l"(b), "l"(c)); return d;
}
__device__ __forceinline__ float sigmoidf_(float v) { return 1.f / (1.f + expf(-v)); }

__device__ __forceinline__ void cp4(uint32_t dst, const float* src, bool p) {
    int sz = p ? 4 : 0;
    asm volatile("cp.async.ca.shared.global [%0], [%1], 4, %2;\n" :: "r"(dst), "l"(src), "r"(sz));
}
__device__ __forceinline__ void cp16(uint32_t dst, const void* src) {
    asm volatile("cp.async.cg.shared.global [%0], [%1], 16;\n" :: "r"(dst), "l"(src));
}
__device__ __forceinline__ void cp_commit() { asm volatile("cp.async.commit_group;\n"); }
template<int N> __device__ __forceinline__ void cp_wait() {
    asm volatile("cp.async.wait_group %0;\n" :: "n"(N));
}
__device__ __forceinline__ void mma16816(float* d, unsigned a0, unsigned a1,
                                         unsigned a2, unsigned a3, unsigned b0, unsigned b1) {
    asm("mma.sync.aligned.m16n8k16.row.col.f32.bf16.bf16.f32 "
        "{%0,%1,%2,%3}, {%4,%5,%6,%7}, {%8,%9}, {%0,%1,%2,%3};"
        : "+f"(d[0]), "+f"(d[1]), "+f"(d[2]), "+f"(d[3])
        : "r"(a0), "r"(a1), "r"(a2), "r"(a3), "r"(b0), "r"(b1));
}

__global__ void transpose_w_kernel(const float* __restrict__ w, float* __restrict__ wt,
                                   int Cin, int K, int Cout)
{
    int i = blockIdx.x * blockDim.x + threadIdx.x;
    if (i >= Cout * Cin * K) return;
    int oc = i / (Cin * K);
    int rem = i - oc * (Cin * K);
    int ci = rem / K, k = rem - (rem / K) * K;
    wt[(ci * K + k) * Cout + oc] = w[i];
}

// identity pack (R9-proven)
__global__ void wpack_kernel(const float* __restrict__ w, unsigned* __restrict__ whi,
                             unsigned* __restrict__ wlo, int Cin, int Cout)
{
    int i = blockIdx.x * blockDim.x + threadIdx.x;
    if (i >= (Cin / 2) * 25 * Cout) return;
    int oc = i % Cout;
    int pr = i / Cout;
    int cb = pr / 200, r2 = pr - cb * 200;
    int k = r2 >> 3, q = r2 & 7;
    int ch0 = cb * 16 + 2 * q;
    float w0 = w[(oc * Cin + ch0) * 25 + k];
    float w1 = w[(oc * Cin + ch0 + 1) * 25 + k];
    unsigned hp; asm("cvt.rn.bf16x2.f32 %0, %1, %2;" : "=r"(hp) : "f"(w1), "f"(w0));
    float r0 = w0 - __uint_as_float(hp << 16);
    float r1 = w1 - __uint_as_float(hp & 0xFFFF0000u);
    unsigned lp; asm("cvt.rn.bf16x2.f32 %0, %1, %2;" : "=r"(lp) : "f"(r1), "f"(r0));
    whi[i] = hp; wlo[i] = lp;
}

// ---------------------------------------------------------------------------
// Tensor-core ConvGRU conv (k5,p2), Cin=2C. CTA: 16x16 px tile x (NF*8) oc.
// 8 warps, warp = 2 tile-rows x all oc. mma m16n8k16, triple-pass hi/lo.
// Scalar conflict-free LDS for A and B (R9-proven configuration).
// ---------------------------------------------------------------------------
template<int MODE, int NF>
__global__ __launch_bounds__(256) void conv5_mma_kernel(
    const float* __restrict__ x, const float* __restrict__ srcB,
    const unsigned* __restrict__ whi, const unsigned* __restrict__ wlo,
    const float* __restrict__ bias,
    float* __restrict__ zbuf, float* __restrict__ hbuf, float* __restrict__ outbuf,
    int C, int H, int W)
{
    constexpr int OCW = NF * 8;
    constexpr int BP = OCW + 8, BCH = 5 * 8 * BP;
    constexpr int WCHUNKS = 160 * NF;
    constexpr int WS = (WCHUNKS + 255) / 256;
    extern __shared__ char sm[];
    float*    s_f = (float*)sm;
    unsigned* s_a = (unsigned*)(sm + 25600);
    unsigned* s_b = (unsigned*)(sm + 25600 + 32000);
    const uint32_t sf0 = (uint32_t)__cvta_generic_to_shared(s_f);
    const uint32_t sb0 = (uint32_t)__cvta_generic_to_shared(s_b);

    const int Cout = (MODE == 0) ? 2 * C : C;
    const int nOcB = Cout / OCW;
    const int bx = blockIdx.x, by = blockIdx.y;
    const int ocB = blockIdx.z % nOcB, bb = blockIdx.z / nOcB;
    const int oc0 = ocB * OCW;
    const int tid = threadIdx.x;
    const int warp = tid >> 5, lane = tid & 31;
    const int g = lane >> 2, tig = lane & 3;
    const int wrow = warp * 2;
    const int hw = H * W;

    int t_g0, t_g1; bool t_v0, t_v1;
    {
        int r = tid / 20, c = tid - r * 20;
        int ih = by * 16 - 2 + r, iw = bx * 16 - 2 + c;
        t_v0 = ((unsigned)ih < (unsigned)H) && ((unsigned)iw < (unsigned)W);
        t_g0 = ih * W + iw;
        int p = tid + 256; r = p / 20; c = p - r * 20;
        ih = by * 16 - 2 + r; iw = bx * 16 - 2 + c;
        t_v1 = (p < 400) && ((unsigned)ih < (unsigned)H) && ((unsigned)iw < (unsigned)W);
        t_g1 = ih * W + iw;
    }
    int wsrc[WS]; uint32_t wdst[WS]; int whl[WS]; bool wact[WS];
    #pragma unroll
    for (int s = 0; s < WS; s++) {
        int j = tid + s * 256;
        wact[s] = j < WCHUNKS;
        if (!wact[s]) j = 0;
        int hl = j / (WCHUNKS / 2), r = j % (WCHUNKS / 2);
        int tap = r / (2 * NF * 8), r2 = r % (2 * NF * 8);
        int q = r2 / (2 * NF), c4 = r2 % (2 * NF);
        whl[s] = hl;
        wsrc[s] = (tap * 8 + q) * Cout + oc0 + c4 * 4;
        wdst[s] = (uint32_t)(hl * BCH + (tap * 8 + q) * BP + c4 * 4);
    }

    const float* xb  = x    + (long)bb * C * hw;
    const float* sbp = srcB + (long)bb * C * hw;
    const int nB = C >> 3;

    auto issueA = [&](int cb) {
        const float* base = (cb * 16 < C) ? (xb + (long)(cb * 16) * hw)
                                          : (sbp + (long)(cb * 16 - C) * hw);
        #pragma unroll
        for (int u = 0; u < 16; u++) {
            const float* bu = base + (long)u * hw;
            cp4(sf0 + (uint32_t)(u * 400 + tid) * 4, bu + (t_v0 ? t_g0 : 0), t_v0);
            if (tid < 144)
                cp4(sf0 + (uint32_t)(u * 400 + 256 + tid) * 4, bu + (t_v1 ? t_g1 : 0), t_v1);
        }
    };
    auto issueB = [&](int cb, int kh, int buf) {
        int off = (cb * 25 + kh * 5) * 8 * Cout;
        #pragma unroll
        for (int s = 0; s < WS; s++) {
            if (wact[s])
                cp16(sb0 + (uint32_t)(buf * 2 * BCH + wdst[s]) * 4,
                     (whl[s] ? wlo : whi) + off + wsrc[s]);
        }
    };

    float acc[2][NF][4];
    #pragma unroll
    for (int rp = 0; rp < 2; rp++)
        #pragma unroll
        for (int f = 0; f < NF; f++)
            #pragma unroll
            for (int e = 0; e < 4; e++) acc[rp][f][e] = 0.f;

    issueA(0); issueB(0, 0, 0); cp_commit();

    for (int cb = 0; cb < nB; cb++) {
        for (int kh = 0; kh < 5; kh++) {
            const int L = cb * 5 + kh, bbuf = L & 1;
            cp_wait<0>();
            __syncthreads();
            if (kh == 0) {
                for (int idx = tid; idx < 3200; idx += 256) {
                    int cp = idx / 400, px = idx - cp * 400;
                    float f0 = s_f[(2 * cp) * 400 + px];
                    float f1 = s_f[(2 * cp + 1) * 400 + px];
                    unsigned hp; asm("cvt.rn.bf16x2.f32 %0, %1, %2;" : "=r"(hp) : "f"(f1), "f"(f0));
                    float r0 = f0 - __uint_as_float(hp << 16);
                    float r1 = f1 - __uint_as_float(hp & 0xFFFF0000u);
                    unsigned lp; asm("cvt.rn.bf16x2.f32 %0, %1, %2;" : "=r"(lp) : "f"(r1), "f"(r0));
                    s_a[px * 20 + cp] = hp;
                    s_a[px * 20 + 8 + cp] = lp;
                }
                __syncthreads();
            }
            if (kh == 4) { if (cb + 1 < nB) issueB(cb + 1, 0, (L + 1) & 1); }
            else {
                issueB(cb, kh + 1, (L + 1) & 1);
                if (kh == 1 && cb + 1 < nB) issueA(cb + 1);
            }
            cp_commit();

            const unsigned* bh = s_b + bbuf * 2 * BCH;
            const unsigned* bl = bh + BCH;
            #pragma unroll
            for (int kw = 0; kw < 5; kw++) {
                unsigned b0h[NF], b1h[NF], b0l[NF], b1l[NF];
                const int br = (kw * 8 + tig) * BP + g;
                #pragma unroll
                for (int f = 0; f < NF; f++) {
                    b0h[f] = bh[br + f * 8]; b1h[f] = bh[br + 4 * BP + f * 8];
                    b0l[f] = bl[br + f * 8]; b1l[f] = bl[br + 4 * BP + f * 8];
                }
                #pragma unroll
                for (int rp = 0; rp < 2; rp++) {
                    const int pxb = (wrow + rp + kh) * 20 + kw;
                    const unsigned* a0 = s_a + (pxb + g) * 20 + tig;
                    const unsigned* a1 = s_a + (pxb + g + 8) * 20 + tig;
                    unsigned ah0 = a0[0], ah1 = a1[0], ah2 = a0[4], ah3 = a1[4];
                    unsigned al0 = a0[8], al1 = a1[8], al2 = a0[12], al3 = a1[12];
                    #pragma unroll
                    for (int f = 0; f < NF; f++) {
                        mma16816(acc[rp][f], ah0, ah1, ah2, ah3, b0h[f], b1h[f]);
                        mma16816(acc[rp][f], al0, al1, al2, al3, b0h[f], b1h[f]);
                        mma16816(acc[rp][f], ah0, ah1, ah2, ah3, b0l[f], b1l[f]);
                    }
                }
            }
        }
    }
    __syncthreads();

    const int row0 = by * 16 + wrow, colg = bx * 16 + g;
    #pragma unroll
    for (int rp = 0; rp < 2; rp++) {
        int row = row0 + rp;
        #pragma unroll
        for (int f = 0; f < NF; f++) {
            int ocx = oc0 + f * 8 + 2 * tig;
            float b0 = bias[ocx], b1 = bias[ocx + 1];
            float d0 = acc[rp][f][0], d1 = acc[rp][f][1];
            float d2 = acc[rp][f][2], d3 = acc[rp][f][3];
            if (MODE == 0) {
                if (ocx < C) {
                    long i0 = ((long)(bb * C + ocx)) * hw + row * W + colg;
                    long i1 = i0 + hw;
                    zbuf[i0]     = sigmoidf_(d0 + b0);
                    zbuf[i0 + 8] = sigmoidf_(d2 + b0);
                    zbuf[i1]     = sigmoidf_(d1 + b1);
                    zbuf[i1 + 8] = sigmoidf_(d3 + b1);
                } else {
                    long i0 = ((long)(bb * C + (ocx - C))) * hw + row * W + colg;
                    long i1 = i0 + hw;
                    outbuf[i0]     = sigmoidf_(d0 + b0) * hbuf[i0];
                    outbuf[i0 + 8] = sigmoidf_(d2 + b0) * hbuf[i0 + 8];
                    outbuf[i1]     = sigmoidf_(d1 + b1) * hbuf[i1];
                    outbuf[i1 + 8] = sigmoidf_(d3 + b1) * hbuf[i1 + 8];
                }
            } else {
                long i0 = ((long)(bb * C + ocx)) * hw + row * W + colg;
                long i1 = i0 + hw;
                float za = zbuf[i0], zb = zbuf[i0 + 8], zc = zbuf[i1], zd = zbuf[i1 + 8];
                float ha = hbuf[i0], hb = hbuf[i0 + 8], hc = hbuf[i1], hd = hbuf[i1 + 8];
                hbuf[i0]     = (1.f - za) * ha + za * tanhf(d0 + b0);
                hbuf[i0 + 8] = (1.f - zb) * hb + zb * tanhf(d2 + b0);
                hbuf[i1]     = (1.f - zc) * hc + zc * tanhf(d1 + b1);
                hbuf[i1 + 8] = (1.f - zd) * hd + zd * tanhf(d3 + b1);
            }
        }
    }
}

#define C5_SMEM(NF) (25600 + 32000 + 2*2*(5*8*((NF)*8+8))*4)

// ---------------------------------------------------------------------------
// fp32 strided conv k4s2p1 (c2/c3), proven R6 kernel.
// ---------------------------------------------------------------------------
template<int PX, int OCB>
__global__ __launch_bounds__((256/PX)*(OCB/8), 3) void conv4s2_kernel(
    const float* __restrict__ x, const float* __restrict__ wt,
    const float* __restrict__ bias, float* __restrict__ y,
    int Cin, int Cout, int Hin, int Win)
{
    constexpr int NPX = 256 / PX, NT = NPX * (OCB / 8);
    constexpr int TILE = 2448, TS = (TILE + NT - 1) / NT;
    constexpr int WW = 32 * OCB, WCH = WW / 4, WS = (WCH + NT - 1) / NT;
    constexpr int LD4 = (2 * PX + 2 + 3) / 4;

    const int Hout = Hin >> 1, Wout = Win >> 1;
    const int nOcB = Cout / OCB;
    const int bx = blockIdx.x, by = blockIdx.y;
    const int ocB = blockIdx.z % nOcB, bb = blockIdx.z / nOcB;
    const int oc0 = ocB * OCB;
    const int tid = threadIdx.x;
    const int pxg = tid % NPX, ocg = tid / NPX;
    const int ty = pxg / (16 / PX), x0 = (pxg % (16 / PX)) * PX;
    const int oh = by * 16 + ty, ow0 = bx * 16 + x0;
    const int ocb = oc0 + ocg * 8;
    const int hwin = Hin * Win;

    __shared__ float s_in[2][TILE];
    __shared__ float s_w[2][WW];
    const uint32_t sin0 = (uint32_t)__cvta_generic_to_shared(&s_in[0][0]);
    const uint32_t sw0  = (uint32_t)__cvta_generic_to_shared(&s_w[0][0]);

    int t_src[TS];
    #pragma unroll
    for (int s = 0; s < TS; s++) {
        int idx = tid + s * NT;
        int u = idx / 1224, pos = idx - u * 1224;
        int r = pos / 36, c = pos - r * 36;
        int ih = by * 32 - 1 + r, iw = bx * 32 - 1 + c;
        bool v = (idx < TILE) && (c < 34) && ((unsigned)ih < (unsigned)Hin) &&
                 ((unsigned)iw < (unsigned)Win);
        t_src[s] = v ? (u * hwin + ih * Win + iw) : -1;
    }
    int w_src[WS];
    #pragma unroll
    for (int s = 0; s < WS; s++) {
        int idx = tid + s * NT;
        bool act = idx < WCH;
        int u = idx / (16 * (OCB / 4)), rm = idx % (16 * (OCB / 4));
        int k = rm / (OCB / 4), c4 = rm % (OCB / 4);
        if (u > 1) u = 1;
        w_src[s] = act ? ((u * 16 + k) * Cout + oc0 + 4 * c4) : -1;
    }

    const float* xb = x + (long)bb * Cin * hwin;
    const int nB = Cin >> 1;

    auto issue = [&](int cb, int buf) {
        const float* base = xb + (long)(cb * 2) * hwin;
        #pragma unroll
        for (int s = 0; s < TS; s++) {
            if ((s + 1) * NT <= TILE || tid + s * NT < TILE) {
                int so = t_src[s];
                cp4(sin0 + (uint32_t)(buf * TILE + tid + s * NT) * 4,
                    base + (so < 0 ? 0 : so), so >= 0);
            }
        }
        const float* wb = wt + (size_t)cb * 32 * Cout;
        #pragma unroll
        for (int s = 0; s < WS; s++)
            if (w_src[s] >= 0)
                cp16(sw0 + (uint32_t)(buf * WW + (tid + s * NT) * 4) * 4, wb + w_src[s]);
        cp_commit();
    };

    ull acc[PX][4];
    #pragma unroll
    for (int p = 0; p < PX; p++)
        #pragma unroll
        for (int j = 0; j < 4; j++) acc[p][j] = 0ULL;

    issue(0, 0);
    for (int cb = 0; cb < nB; cb++) {
        const int buf = cb & 1;
        if (cb + 1 < nB) { issue(cb + 1, buf ^ 1); cp_wait<1>(); }
        else cp_wait<0>();
        __syncthreads();
        #pragma unroll
        for (int u = 0; u < 2; u++) {
            #pragma unroll
            for (int kh = 0; kh < 4; kh++) {
                const float4* rp = (const float4*)&s_in[buf][u * 1224 + (2 * ty + kh) * 36 + 2 * x0];
                float xr[4 * LD4];
                #pragma unroll
                for (int q = 0; q < LD4; q++) {
                    float4 t = rp[q];
                    xr[4*q] = t.x; xr[4*q+1] = t.y; xr[4*q+2] = t.z; xr[4*q+3] = t.w;
                }
                ull vx[2 * PX + 2];
                #pragma unroll
                for (int m = 0; m < 2 * PX + 2; m++) vx[m] = pack2(xr[m], xr[m]);
                #pragma unroll
                for (int kw = 0; kw < 4; kw++) {
                    const ulonglong2* wp = (const ulonglong2*)&s_w[buf][(u * 16 + kh * 4 + kw) * OCB + ocg * 8];
                    ulonglong2 wA = wp[0], wB = wp[1];
                    #pragma unroll
                    for (int p = 0; p < PX; p++) {
                        acc[p][0] = ffma2(wA.x, vx[kw + 2*p], acc[p][0]);
                        acc[p][1] = ffma2(wA.y, vx[kw + 2*p], acc[p][1]);
                        acc[p][2] = ffma2(wB.x, vx[kw + 2*p], acc[p][2]);
                        acc[p][3] = ffma2(wB.y, vx[kw + 2*p], acc[p][3]);
                    }
                }
            }
        }
        __syncthreads();
    }

    float val[8][PX];
    #pragma unroll
    for (int p = 0; p < PX; p++)
        #pragma unroll
        for (int jp = 0; jp < 4; jp++)
            unpack2(acc[p][jp], val[2*jp][p], val[2*jp+1][p]);

    const long hwout = (long)Hout * Wout;
    #pragma unroll
    for (int j = 0; j < 8; j++) {
        int oc = ocb + j;
        float b = bias[oc];
        #pragma unroll
        for (int q = 0; q < PX / 4; q++) {
            float4 o = make_float4(val[j][4*q+0] + b, val[j][4*q+1] + b,
                                   val[j][4*q+2] + b, val[j][4*q+3] + b);
            *(float4*)&y[((long)bb * Cout + oc) * hwout + (long)oh * Wout + ow0 + 4*q] = o;
        }
    }
}

__global__ __launch_bounds__(256) void conv4s2_c1_kernel(
    const float* __restrict__ x, long xbstride,
    const float* __restrict__ w, const float* __restrict__ bias,
    float* __restrict__ y, int Cout, int Hin, int Win)
{
    const int Hout = Hin >> 1, Wout = Win >> 1;
    const int nog = Cout >> 2;
    const int bx = blockIdx.x, by = blockIdx.y;
    const int ocg = blockIdx.z % nog, bb = blockIdx.z / nog;
    const int tx = threadIdx.x, ty = threadIdx.y;
    const int tid = ty * 16 + tx;
    const int oh = by * 16 + ty, ow = bx * 16 + tx;

    __shared__ float s_in[34 * 34];
    __shared__ float4 s_w4[16];

    float a0 = 0.f, a1 = 0.f, a2 = 0.f, a3 = 0.f;
    const int ih0 = by * 32 - 1, iw0 = bx * 32 - 1;
    const int oc0 = ocg * 4;
    const float* xc = x + (long)bb * xbstride;

    for (int i = tid; i < 34 * 34; i += 256) {
        int r = i / 34, c = i - r * 34;
        int ih = ih0 + r, iw = iw0 + c;
        float v = 0.f;
        if ((unsigned)ih < (unsigned)Hin && (unsigned)iw < (unsigned)Win)
            v = xc[ih * Win + iw];
        s_in[i] = v;
    }
    if (tid < 64) {
        int k = tid >> 2, j = tid & 3;
        ((float*)s_w4)[k * 4 + j] = w[(oc0 + j) * 16 + k];
    }
    __syncthreads();
    #pragma unroll
    for (int kh = 0; kh < 4; kh++)
        #pragma unroll
        for (int kw = 0; kw < 4; kw++) {
            float v = s_in[(2 * ty + kh) * 34 + 2 * tx + kw];
            float4 wv = s_w4[kh * 4 + kw];
            a0 += v * wv.x; a1 += v * wv.y; a2 += v * wv.z; a3 += v * wv.w;
        }
    const long cs = (long)Hout * Wout;
    long base = (((long)bb * Cout + oc0) * Hout + oh) * Wout + ow;
    y[base] = a0 + bias[oc0];           y[base + cs] = a1 + bias[oc0 + 1];
    y[base + 2 * cs] = a2 + bias[oc0 + 2]; y[base + 3 * cs] = a3 + bias[oc0 + 3];
}

__global__ void copyout_kernel(const float* __restrict__ a, int na,
                               const float* __restrict__ b, int nb,
                               const float* __restrict__ c, int nc,
                               float* __restrict__ out)
{
    int i = blockIdx.x * blockDim.x + threadIdx.x;
    if (i < na) out[i] = a[i];
    else if (i < na + nb) out[i] = b[i - na];
    else if (i < na + nb + nc) out[i] = c[i - na - nb];
}

extern "C" void kernel_launch(void* const* d_in, const int* in_sizes, int n_in,
                              void* d_out, int out_size)
{
    const float* input   = (const float*)d_in[0];
    const float* c1_w    = (const float*)d_in[1];
    const float* c1_b    = (const float*)d_in[2];
    const float* g1_zr_w = (const float*)d_in[3];
    const float* g1_zr_b = (const float*)d_in[4];
    const float* g1_h_w  = (const float*)d_in[5];
    const float* g1_h_b  = (const float*)d_in[6];
    const float* c2_w    = (const float*)d_in[7];
    const float* c2_b    = (const float*)d_in[8];
    const float* g2_zr_w = (const float*)d_in[9];
    const float* g2_zr_b = (const float*)d_in[10];
    const float* g2_h_w  = (const float*)d_in[11];
    const float* g2_h_b  = (const float*)d_in[12];
    const float* c3_w    = (const float*)d_in[13];
    const float* c3_b    = (const float*)d_in[14];
    const float* g3_zr_w = (const float*)d_in[15];
    const float* g3_zr_b = (const float*)d_in[16];
    const float* g3_h_w  = (const float*)d_in[17];
    const float* g3_h_b  = (const float*)d_in[18];

    float *h1, *x1, *z1, *rh1, *h2, *x2, *z2, *rh2, *h3, *x3, *z3, *rh3;
    cudaGetSymbolAddress((void**)&h1, g_h1);   cudaGetSymbolAddress((void**)&x1, g_x1);
    cudaGetSymbolAddress((void**)&z1, g_z1);   cudaGetSymbolAddress((void**)&rh1, g_rh1);
    cudaGetSymbolAddress((void**)&h2, g_h2);   cudaGetSymbolAddress((void**)&x2, g_x2);
    cudaGetSymbolAddress((void**)&z2, g_z2);   cudaGetSymbolAddress((void**)&rh2, g_rh2);
    cudaGetSymbolAddress((void**)&h3, g_h3);   cudaGetSymbolAddress((void**)&x3, g_x3);
    cudaGetSymbolAddress((void**)&z3, g_z3);   cudaGetSymbolAddress((void**)&rh3, g_rh3);

    float *wt_c2, *wt_c3;
    cudaGetSymbolAddress((void**)&wt_c2, g_wt_c2);
    cudaGetSymbolAddress((void**)&wt_c3, g_wt_c3);
    unsigned *whzr1,*wlzr1,*whh1,*wlh1,*whzr2,*wlzr2,*whh2,*wlh2,*whzr3,*wlzr3,*whh3,*wlh3;
    cudaGetSymbolAddress((void**)&whzr1, g_wh_zr1); cudaGetSymbolAddress((void**)&wlzr1, g_wl_zr1);
    cudaGetSymbolAddress((void**)&whh1,  g_wh_h1);  cudaGetSymbolAddress((void**)&wlh1,  g_wl_h1);
    cudaGetSymbolAddress((void**)&whzr2, g_wh_zr2); cudaGetSymbolAddress((void**)&wlzr2, g_wl_zr2);
    cudaGetSymbolAddress((void**)&whh2,  g_wh_h2);  cudaGetSymbolAddress((void**)&wlh2,  g_wl_h2);
    cudaGetSymbolAddress((void**)&whzr3, g_wh_zr3); cudaGetSymbolAddress((void**)&wlzr3, g_wl_zr3);
    cudaGetSymbolAddress((void**)&whh3,  g_wh_h3);  cudaGetSymbolAddress((void**)&wlh3,  g_wl_h3);

    cudaFuncSetAttribute(conv5_mma_kernel<0,4>, cudaFuncAttributeMaxDynamicSharedMemorySize, C5_SMEM(4));
    cudaFuncSetAttribute(conv5_mma_kernel<1,4>, cudaFuncAttributeMaxDynamicSharedMemorySize, C5_SMEM(4));
    cudaFuncSetAttribute(conv5_mma_kernel<0,2>, cudaFuncAttributeMaxDynamicSharedMemorySize, C5_SMEM(2));
    cudaFuncSetAttribute(conv5_mma_kernel<1,2>, cudaFuncAttributeMaxDynamicSharedMemorySize, C5_SMEM(2));

    // one-time stream/event creation (host resources only; GPU work identical
    // every call, so the captured graph is the same on every capture)
    static cudaStream_t sA = nullptr, sB = nullptr, sC = nullptr;
    static cudaEvent_t evS, evA, evB, evC2, evC3, evE1, evE2, evE3;
    if (!sA) {
        cudaStreamCreateWithFlags(&sA, cudaStreamNonBlocking);
        cudaStreamCreateWithFlags(&sB, cudaStreamNonBlocking);
        cudaStreamCreateWithFlags(&sC, cudaStreamNonBlocking);
        cudaEventCreateWithFlags(&evS,  cudaEventDisableTiming);
        cudaEventCreateWithFlags(&evA,  cudaEventDisableTiming);
        cudaEventCreateWithFlags(&evB,  cudaEventDisableTiming);
        cudaEventCreateWithFlags(&evC2, cudaEventDisableTiming);
        cudaEventCreateWithFlags(&evC3, cudaEventDisableTiming);
        cudaEventCreateWithFlags(&evE1, cudaEventDisableTiming);
        cudaEventCreateWithFlags(&evE2, cudaEventDisableTiming);
        cudaEventCreateWithFlags(&evE3, cudaEventDisableTiming);
    }

    cudaMemsetAsync(h1, 0, (size_t)S1_N * sizeof(float), 0);
    cudaMemsetAsync(h2, 0, (size_t)S2_N * sizeof(float), 0);
    cudaMemsetAsync(h3, 0, (size_t)S3_N * sizeof(float), 0);

    auto tr = [](const float* w, float* wt, int Cin, int K, int Cout) {
        int n = Cout * Cin * K;
        transpose_w_kernel<<<(n + 255) / 256, 256>>>(w, wt, Cin, K, Cout);
    };
    tr(c2_w, wt_c2, 64, 16, 128);
    tr(c3_w, wt_c3, 128, 16, 128);
    auto wp = [](const float* w, unsigned* wh, unsigned* wl, int Cin, int Cout) {
        int n = (Cin / 2) * 25 * Cout;
        wpack_kernel<<<(n + 255) / 256, 256>>>(w, wh, wl, Cin, Cout);
    };
    wp(g1_zr_w, whzr1, wlzr1, 128, 128);
    wp(g1_h_w,  whh1,  wlh1,  128, 64);
    wp(g2_zr_w, whzr2, wlzr2, 256, 256);
    wp(g2_h_w,  whh2,  wlh2,  256, 128);
    wp(g3_zr_w, whzr3, wlzr3, 256, 256);
    wp(g3_h_w,  whh3,  wlh3,  256, 128);

    // fork the three stage streams off the capture stream
    cudaEventRecord(evS, 0);
    cudaStreamWaitEvent(sA, evS, 0);
    cudaStreamWaitEvent(sB, evS, 0);
    cudaStreamWaitEvent(sC, evS, 0);

    const long in_bstride = (long)12 * 128 * 128;

    for (int t = 0; t < 12; t++) {
        // ---- stream A: stage 1 ----
        conv4s2_c1_kernel<<<dim3(4, 4, 8 * 16), dim3(16, 16), 0, sA>>>(
            input + (long)t * 128 * 128, in_bstride, c1_w, c1_b, x1, 64, 128, 128);
        conv5_mma_kernel<0,4><<<dim3(4, 4, 8 * 4), 256, C5_SMEM(4), sA>>>(
            x1, h1, whzr1, wlzr1, g1_zr_b, z1, h1, rh1, 64, 64, 64);
        if (t > 0) cudaStreamWaitEvent(sA, evC2, 0);     // c2(t-1) must finish reading h1
        conv5_mma_kernel<1,4><<<dim3(4, 4, 8 * 2), 256, C5_SMEM(4), sA>>>(
            x1, rh1, whh1, wlh1, g1_h_b, z1, h1, nullptr, 64, 64, 64);
        cudaEventRecord(evA, sA);
        // ---- stream B: stage 2 ----
        cudaStreamWaitEvent(sB, evA, 0);                 // h1(t) ready
        conv4s2_kernel<4, 16><<<dim3(2, 2, 8 * 8), 128, 0, sB>>>(
            h1, wt_c2, c2_b, x2, 64, 128, 64, 64);
        cudaEventRecord(evC2, sB);                       // h1 consumed
        conv5_mma_kernel<0,4><<<dim3(2, 2, 8 * 8), 256, C5_SMEM(4), sB>>>(
            x2, h2, whzr2, wlzr2, g2_zr_b, z2, h2, rh2, 128, 32, 32);
        if (t > 0) cudaStreamWaitEvent(sB, evC3, 0);     // c3(t-1) must finish reading h2
        conv5_mma_kernel<1,4><<<dim3(2, 2, 8 * 4), 256, C5_SMEM(4), sB>>>(
            x2, rh2, whh2, wlh2, g2_h_b, z2, h2, nullptr, 128, 32, 32);
        cudaEventRecord(evB, sB);
        // ---- stream C: stage 3 (NF=2) ----
        cudaStreamWaitEvent(sC, evB, 0);                 // h2(t) ready
        conv4s2_kernel<4, 16><<<dim3(1, 1, 8 * 8), 128, 0, sC>>>(
            h2, wt_c3, c3_b, x3, 128, 128, 32, 32);
        cudaEventRecord(evC3, sC);                       // h2 consumed
        conv5_mma_kernel<0,2><<<dim3(1, 1, 8 * 16), 256, C5_SMEM(2), sC>>>(
            x3, h3, whzr3, wlzr3, g3_zr_b, z3, h3, rh3, 128, 16, 16);
        conv5_mma_kernel<1,2><<<dim3(1, 1, 8 * 8), 256, C5_SMEM(2), sC>>>(
            x3, rh3, whh3, wlh3, g3_h_b, z3, h3, nullptr, 128, 16, 16);
    }

    // join all three streams back into the capture stream
    cudaEventRecord(evE1, sA);
    cudaEventRecord(evE2, sB);
    cudaEventRecord(evE3, sC);
    cudaStreamWaitEvent(0, evE1, 0);
    cudaStreamWaitEvent(0, evE2, 0);
    cudaStreamWaitEvent(0, evE3, 0);

    const int total = S1_N + S2_N + S3_N;
    copyout_kernel<<<(total + 255) / 256, 256>>>(h1, S1_N, h2, S2_N, h3, S3_N,
                                                 (float*)d_out);
}

// round 15
// speedup vs baseline: 1.5417x; 1.0113x over previous
#include <cuda_runtime.h>
#include <cuda_bf16.h>
#include <math.h>
#include <stdint.h>

#define S1_N (8*64*64*64)
#define S2_N (8*128*32*32)
#define S3_N (8*128*16*16)

__device__ float g_h1[S1_N], g_z1[S1_N], g_rh1[S1_N];
__device__ float g_x1b[12 * S1_N];           // all-timestep c1 outputs
__device__ float g_h2[S2_N], g_x2[S2_N], g_z2[S2_N], g_rh2[S2_N];
__device__ float g_h3[S3_N], g_x3[S3_N], g_z3[S3_N], g_rh3[S3_N];

__device__ float g_wt_c2[64*16*128];
__device__ float g_wt_c3[128*16*128];

// bf16 hi/lo packed gate weights (identity layout):
// [( (cb*25+k)*8 + q )*Cout + oc], pair = (ch 2q, ch 2q+1)
__device__ unsigned g_wh_zr1[64*25*128],  g_wl_zr1[64*25*128];
__device__ unsigned g_wh_h1 [64*25*64],   g_wl_h1 [64*25*64];
__device__ unsigned g_wh_zr2[128*25*256], g_wl_zr2[128*25*256];
__device__ unsigned g_wh_h2 [128*25*128], g_wl_h2 [128*25*128];
__device__ unsigned g_wh_zr3[128*25*256], g_wl_zr3[128*25*256];
__device__ unsigned g_wh_h3 [128*25*128], g_wl_h3 [128*25*128];

typedef unsigned long long ull;

__device__ __forceinline__ ull pack2(float lo, float hi) {
    ull r; asm("mov.b64 %0, {%1, %2};" : "=l"(r) : "f"(lo), "f"(hi)); return r;
}
__device__ __forceinline__ void unpack2(ull v, float& lo, float& hi) {
    asm("mov.b64 {%0, %1}, %2;" : "=f"(lo), "=f"(hi) : "l"(v));
}
__device__ __forceinline__ ull ffma2(ull a, ull b, ull c) {
    ull d; asm("fma.rn.f32x2 %0, %1, %2, %3;" : "=l"(d) : "l"(a), "l"(b), "l"(c)); return d;
}
__device__ __forceinline__ float sigmoidf_(float v) { return 1.f / (1.f + expf(-v)); }

__device__ __forceinline__ void cp4(uint32_t dst, const float* src, bool p) {
    int sz = p ? 4 : 0;
    asm volatile("cp.async.ca.shared.global [%0], [%1], 4, %2;\n" :: "r"(dst), "l"(src), "r"(sz));
}
__device__ __forceinline__ void cp16(uint32_t dst, const void* src) {
    asm volatile("cp.async.cg.shared.global [%0], [%1], 16;\n" :: "r"(dst), "l"(src));
}
__device__ __forceinline__ void cp_commit() { asm volatile("cp.async.commit_group;\n"); }
template<int N> __device__ __forceinline__ void cp_wait() {
    asm volatile("cp.async.wait_group %0;\n" :: "n"(N));
}
__device__ __forceinline__ void mma16816(float* d, unsigned a0, unsigned a1,
                                         unsigned a2, unsigned a3, unsigned b0, unsigned b1) {
    asm("mma.sync.aligned.m16n8k16.row.col.f32.bf16.bf16.f32 "
        "{%0,%1,%2,%3}, {%4,%5,%6,%7}, {%8,%9}, {%0,%1,%2,%3};"
        : "+f"(d[0]), "+f"(d[1]), "+f"(d[2]), "+f"(d[3])
        : "r"(a0), "r"(a1), "r"(a2), "r"(a3), "r"(b0), "r"(b1));
}

__global__ void transpose_w_kernel(const float* __restrict__ w, float* __restrict__ wt,
                                   int Cin, int K, int Cout)
{
    int i = blockIdx.x * blockDim.x + threadIdx.x;
    if (i >= Cout * Cin * K) return;
    int oc = i / (Cin * K);
    int rem = i - oc * (Cin * K);
    int ci = rem / K, k = rem - (rem / K) * K;
    wt[(ci * K + k) * Cout + oc] = w[i];
}

// identity pack (R9-proven)
__global__ void wpack_kernel(const float* __restrict__ w, unsigned* __restrict__ whi,
                             unsigned* __restrict__ wlo, int Cin, int Cout)
{
    int i = blockIdx.x * blockDim.x + threadIdx.x;
    if (i >= (Cin / 2) * 25 * Cout) return;
    int oc = i % Cout;
    int pr = i / Cout;
    int cb = pr / 200, r2 = pr - cb * 200;
    int k = r2 >> 3, q = r2 & 7;
    int ch0 = cb * 16 + 2 * q;
    float w0 = w[(oc * Cin + ch0) * 25 + k];
    float w1 = w[(oc * Cin + ch0 + 1) * 25 + k];
    unsigned hp; asm("cvt.rn.bf16x2.f32 %0, %1, %2;" : "=r"(hp) : "f"(w1), "f"(w0));
    float r0 = w0 - __uint_as_float(hp << 16);
    float r1 = w1 - __uint_as_float(hp & 0xFFFF0000u);
    unsigned lp; asm("cvt.rn.bf16x2.f32 %0, %1, %2;" : "=r"(lp) : "f"(r1), "f"(r0));
    whi[i] = hp; wlo[i] = lp;
}

// ---------------------------------------------------------------------------
// Tensor-core ConvGRU conv (k5,p2), Cin=2C. CTA: 16x16 px tile x (NF*8) oc.
// 8 warps, warp = 2 tile-rows x all oc. mma m16n8k16, triple-pass hi/lo.
// Scalar conflict-free LDS for A and B (R9-proven configuration).
// ---------------------------------------------------------------------------
template<int MODE, int NF>
__global__ __launch_bounds__(256) void conv5_mma_kernel(
    const float* __restrict__ x, const float* __restrict__ srcB,
    const unsigned* __restrict__ whi, const unsigned* __restrict__ wlo,
    const float* __restrict__ bias,
    float* __restrict__ zbuf, float* __restrict__ hbuf, float* __restrict__ outbuf,
    int C, int H, int W)
{
    constexpr int OCW = NF * 8;
    constexpr int BP = OCW + 8, BCH = 5 * 8 * BP;
    constexpr int WCHUNKS = 160 * NF;
    constexpr int WS = (WCHUNKS + 255) / 256;
    extern __shared__ char sm[];
    float*    s_f = (float*)sm;
    unsigned* s_a = (unsigned*)(sm + 25600);
    unsigned* s_b = (unsigned*)(sm + 25600 + 32000);
    const uint32_t sf0 = (uint32_t)__cvta_generic_to_shared(s_f);
    const uint32_t sb0 = (uint32_t)__cvta_generic_to_shared(s_b);

    const int Cout = (MODE == 0) ? 2 * C : C;
    const int nOcB = Cout / OCW;
    const int bx = blockIdx.x, by = blockIdx.y;
    const int ocB = blockIdx.z % nOcB, bb = blockIdx.z / nOcB;
    const int oc0 = ocB * OCW;
    const int tid = threadIdx.x;
    const int warp = tid >> 5, lane = tid & 31;
    const int g = lane >> 2, tig = lane & 3;
    const int wrow = warp * 2;
    const int hw = H * W;

    int t_g0, t_g1; bool t_v0, t_v1;
    {
        int r = tid / 20, c = tid - r * 20;
        int ih = by * 16 - 2 + r, iw = bx * 16 - 2 + c;
        t_v0 = ((unsigned)ih < (unsigned)H) && ((unsigned)iw < (unsigned)W);
        t_g0 = ih * W + iw;
        int p = tid + 256; r = p / 20; c = p - r * 20;
        ih = by * 16 - 2 + r; iw = bx * 16 - 2 + c;
        t_v1 = (p < 400) && ((unsigned)ih < (unsigned)H) && ((unsigned)iw < (unsigned)W);
        t_g1 = ih * W + iw;
    }
    int wsrc[WS]; uint32_t wdst[WS]; int whl[WS]; bool wact[WS];
    #pragma unroll
    for (int s = 0; s < WS; s++) {
        int j = tid + s * 256;
        wact[s] = j < WCHUNKS;
        if (!wact[s]) j = 0;
        int hl = j / (WCHUNKS / 2), r = j % (WCHUNKS / 2);
        int tap = r / (2 * NF * 8), r2 = r % (2 * NF * 8);
        int q = r2 / (2 * NF), c4 = r2 % (2 * NF);
        whl[s] = hl;
        wsrc[s] = (tap * 8 + q) * Cout + oc0 + c4 * 4;
        wdst[s] = (uint32_t)(hl * BCH + (tap * 8 + q) * BP + c4 * 4);
    }

    const float* xb  = x    + (long)bb * C * hw;
    const float* sbp = srcB + (long)bb * C * hw;
    const int nB = C >> 3;

    auto issueA = [&](int cb) {
        const float* base = (cb * 16 < C) ? (xb + (long)(cb * 16) * hw)
                                          : (sbp + (long)(cb * 16 - C) * hw);
        #pragma unroll
        for (int u = 0; u < 16; u++) {
            const float* bu = base + (long)u * hw;
            cp4(sf0 + (uint32_t)(u * 400 + tid) * 4, bu + (t_v0 ? t_g0 : 0), t_v0);
            if (tid < 144)
                cp4(sf0 + (uint32_t)(u * 400 + 256 + tid) * 4, bu + (t_v1 ? t_g1 : 0), t_v1);
        }
    };
    auto issueB = [&](int cb, int kh, int buf) {
        int off = (cb * 25 + kh * 5) * 8 * Cout;
        #pragma unroll
        for (int s = 0; s < WS; s++) {
            if (wact[s])
                cp16(sb0 + (uint32_t)(buf * 2 * BCH + wdst[s]) * 4,
                     (whl[s] ? wlo : whi) + off + wsrc[s]);
        }
    };

    float acc[2][NF][4];
    #pragma unroll
    for (int rp = 0; rp < 2; rp++)
        #pragma unroll
        for (int f = 0; f < NF; f++)
            #pragma unroll
            for (int e = 0; e < 4; e++) acc[rp][f][e] = 0.f;

    issueA(0); issueB(0, 0, 0); cp_commit();

    for (int cb = 0; cb < nB; cb++) {
        for (int kh = 0; kh < 5; kh++) {
            const int L = cb * 5 + kh, bbuf = L & 1;
            cp_wait<0>();
            __syncthreads();
            if (kh == 0) {
                for (int idx = tid; idx < 3200; idx += 256) {
                    int cp = idx / 400, px = idx - cp * 400;
                    float f0 = s_f[(2 * cp) * 400 + px];
                    float f1 = s_f[(2 * cp + 1) * 400 + px];
                    unsigned hp; asm("cvt.rn.bf16x2.f32 %0, %1, %2;" : "=r"(hp) : "f"(f1), "f"(f0));
                    float r0 = f0 - __uint_as_float(hp << 16);
                    float r1 = f1 - __uint_as_float(hp & 0xFFFF0000u);
                    unsigned lp; asm("cvt.rn.bf16x2.f32 %0, %1, %2;" : "=r"(lp) : "f"(r1), "f"(r0));
                    s_a[px * 20 + cp] = hp;
                    s_a[px * 20 + 8 + cp] = lp;
                }
                __syncthreads();
            }
            if (kh == 4) { if (cb + 1 < nB) issueB(cb + 1, 0, (L + 1) & 1); }
            else {
                issueB(cb, kh + 1, (L + 1) & 1);
                if (kh == 1 && cb + 1 < nB) issueA(cb + 1);
            }
            cp_commit();

            const unsigned* bh = s_b + bbuf * 2 * BCH;
            const unsigned* bl = bh + BCH;
            #pragma unroll
            for (int kw = 0; kw < 5; kw++) {
                unsigned b0h[NF], b1h[NF], b0l[NF], b1l[NF];
                const int br = (kw * 8 + tig) * BP + g;
                #pragma unroll
                for (int f = 0; f < NF; f++) {
                    b0h[f] = bh[br + f * 8]; b1h[f] = bh[br + 4 * BP + f * 8];
                    b0l[f] = bl[br + f * 8]; b1l[f] = bl[br + 4 * BP + f * 8];
                }
                #pragma unroll
                for (int rp = 0; rp < 2; rp++) {
                    const int pxb = (wrow + rp + kh) * 20 + kw;
                    const unsigned* a0 = s_a + (pxb + g) * 20 + tig;
                    const unsigned* a1 = s_a + (pxb + g + 8) * 20 + tig;
                    unsigned ah0 = a0[0], ah1 = a1[0], ah2 = a0[4], ah3 = a1[4];
                    unsigned al0 = a0[8], al1 = a1[8], al2 = a0[12], al3 = a1[12];
                    #pragma unroll
                    for (int f = 0; f < NF; f++) {
                        mma16816(acc[rp][f], ah0, ah1, ah2, ah3, b0h[f], b1h[f]);
                        mma16816(acc[rp][f], al0, al1, al2, al3, b0h[f], b1h[f]);
                        mma16816(acc[rp][f], ah0, ah1, ah2, ah3, b0l[f], b1l[f]);
                    }
                }
            }
        }
    }
    __syncthreads();

    const int row0 = by * 16 + wrow, colg = bx * 16 + g;
    #pragma unroll
    for (int rp = 0; rp < 2; rp++) {
        int row = row0 + rp;
        #pragma unroll
        for (int f = 0; f < NF; f++) {
            int ocx = oc0 + f * 8 + 2 * tig;
            float b0 = bias[ocx], b1 = bias[ocx + 1];
            float d0 = acc[rp][f][0], d1 = acc[rp][f][1];
            float d2 = acc[rp][f][2], d3 = acc[rp][f][3];
            if (MODE == 0) {
                if (ocx < C) {
                    long i0 = ((long)(bb * C + ocx)) * hw + row * W + colg;
                    long i1 = i0 + hw;
                    zbuf[i0]     = sigmoidf_(d0 + b0);
                    zbuf[i0 + 8] = sigmoidf_(d2 + b0);
                    zbuf[i1]     = sigmoidf_(d1 + b1);
                    zbuf[i1 + 8] = sigmoidf_(d3 + b1);
                } else {
                    long i0 = ((long)(bb * C + (ocx - C))) * hw + row * W + colg;
                    long i1 = i0 + hw;
                    outbuf[i0]     = sigmoidf_(d0 + b0) * hbuf[i0];
                    outbuf[i0 + 8] = sigmoidf_(d2 + b0) * hbuf[i0 + 8];
                    outbuf[i1]     = sigmoidf_(d1 + b1) * hbuf[i1];
                    outbuf[i1 + 8] = sigmoidf_(d3 + b1) * hbuf[i1 + 8];
                }
            } else {
                long i0 = ((long)(bb * C + ocx)) * hw + row * W + colg;
                long i1 = i0 + hw;
                float za = zbuf[i0], zb = zbuf[i0 + 8], zc = zbuf[i1], zd = zbuf[i1 + 8];
                float ha = hbuf[i0], hb = hbuf[i0 + 8], hc = hbuf[i1], hd = hbuf[i1 + 8];
                hbuf[i0]     = (1.f - za) * ha + za * tanhf(d0 + b0);
                hbuf[i0 + 8] = (1.f - zb) * hb + zb * tanhf(d2 + b0);
                hbuf[i1]     = (1.f - zc) * hc + zc * tanhf(d1 + b1);
                hbuf[i1 + 8] = (1.f - zd) * hd + zd * tanhf(d3 + b1);
            }
        }
    }
}

#define C5_SMEM(NF) (25600 + 32000 + 2*2*(5*8*((NF)*8+8))*4)

// ---------------------------------------------------------------------------
// fp32 strided conv k4s2p1 (c2/c3), proven R6 kernel.
// ---------------------------------------------------------------------------
template<int PX, int OCB>
__global__ __launch_bounds__((256/PX)*(OCB/8), 3) void conv4s2_kernel(
    const float* __restrict__ x, const float* __restrict__ wt,
    const float* __restrict__ bias, float* __restrict__ y,
    int Cin, int Cout, int Hin, int Win)
{
    constexpr int NPX = 256 / PX, NT = NPX * (OCB / 8);
    constexpr int TILE = 2448, TS = (TILE + NT - 1) / NT;
    constexpr int WW = 32 * OCB, WCH = WW / 4, WS = (WCH + NT - 1) / NT;
    constexpr int LD4 = (2 * PX + 2 + 3) / 4;

    const int Hout = Hin >> 1, Wout = Win >> 1;
    const int nOcB = Cout / OCB;
    const int bx = blockIdx.x, by = blockIdx.y;
    const int ocB = blockIdx.z % nOcB, bb = blockIdx.z / nOcB;
    const int oc0 = ocB * OCB;
    const int tid = threadIdx.x;
    const int pxg = tid % NPX, ocg = tid / NPX;
    const int ty = pxg / (16 / PX), x0 = (pxg % (16 / PX)) * PX;
    const int oh = by * 16 + ty, ow0 = bx * 16 + x0;
    const int ocb = oc0 + ocg * 8;
    const int hwin = Hin * Win;

    __shared__ float s_in[2][TILE];
    __shared__ float s_w[2][WW];
    const uint32_t sin0 = (uint32_t)__cvta_generic_to_shared(&s_in[0][0]);
    const uint32_t sw0  = (uint32_t)__cvta_generic_to_shared(&s_w[0][0]);

    int t_src[TS];
    #pragma unroll
    for (int s = 0; s < TS; s++) {
        int idx = tid + s * NT;
        int u = idx / 1224, pos = idx - u * 1224;
        int r = pos / 36, c = pos - r * 36;
        int ih = by * 32 - 1 + r, iw = bx * 32 - 1 + c;
        bool v = (idx < TILE) && (c < 34) && ((unsigned)ih < (unsigned)Hin) &&
                 ((unsigned)iw < (unsigned)Win);
        t_src[s] = v ? (u * hwin + ih * Win + iw) : -1;
    }
    int w_src[WS];
    #pragma unroll
    for (int s = 0; s < WS; s++) {
        int idx = tid + s * NT;
        bool act = idx < WCH;
        int u = idx / (16 * (OCB / 4)), rm = idx % (16 * (OCB / 4));
        int k = rm / (OCB / 4), c4 = rm % (OCB / 4);
        if (u > 1) u = 1;
        w_src[s] = act ? ((u * 16 + k) * Cout + oc0 + 4 * c4) : -1;
    }

    const float* xb = x + (long)bb * Cin * hwin;
    const int nB = Cin >> 1;

    auto issue = [&](int cb, int buf) {
        const float* base = xb + (long)(cb * 2) * hwin;
        #pragma unroll
        for (int s = 0; s < TS; s++) {
            if ((s + 1) * NT <= TILE || tid + s * NT < TILE) {
                int so = t_src[s];
                cp4(sin0 + (uint32_t)(buf * TILE + tid + s * NT) * 4,
                    base + (so < 0 ? 0 : so), so >= 0);
            }
        }
        const float* wb = wt + (size_t)cb * 32 * Cout;
        #pragma unroll
        for (int s = 0; s < WS; s++)
            if (w_src[s] >= 0)
                cp16(sw0 + (uint32_t)(buf * WW + (tid + s * NT) * 4) * 4, wb + w_src[s]);
        cp_commit();
    };

    ull acc[PX][4];
    #pragma unroll
    for (int p = 0; p < PX; p++)
        #pragma unroll
        for (int j = 0; j < 4; j++) acc[p][j] = 0ULL;

    issue(0, 0);
    for (int cb = 0; cb < nB; cb++) {
        const int buf = cb & 1;
        if (cb + 1 < nB) { issue(cb + 1, buf ^ 1); cp_wait<1>(); }
        else cp_wait<0>();
        __syncthreads();
        #pragma unroll
        for (int u = 0; u < 2; u++) {
            #pragma unroll
            for (int kh = 0; kh < 4; kh++) {
                const float4* rp = (const float4*)&s_in[buf][u * 1224 + (2 * ty + kh) * 36 + 2 * x0];
                float xr[4 * LD4];
                #pragma unroll
                for (int q = 0; q < LD4; q++) {
                    float4 t = rp[q];
                    xr[4*q] = t.x; xr[4*q+1] = t.y; xr[4*q+2] = t.z; xr[4*q+3] = t.w;
                }
                ull vx[2 * PX + 2];
                #pragma unroll
                for (int m = 0; m < 2 * PX + 2; m++) vx[m] = pack2(xr[m], xr[m]);
                #pragma unroll
                for (int kw = 0; kw < 4; kw++) {
                    const ulonglong2* wp = (const ulonglong2*)&s_w[buf][(u * 16 + kh * 4 + kw) * OCB + ocg * 8];
                    ulonglong2 wA = wp[0], wB = wp[1];
                    #pragma unroll
                    for (int p = 0; p < PX; p++) {
                        acc[p][0] = ffma2(wA.x, vx[kw + 2*p], acc[p][0]);
                        acc[p][1] = ffma2(wA.y, vx[kw + 2*p], acc[p][1]);
                        acc[p][2] = ffma2(wB.x, vx[kw + 2*p], acc[p][2]);
                        acc[p][3] = ffma2(wB.y, vx[kw + 2*p], acc[p][3]);
                    }
                }
            }
        }
        __syncthreads();
    }

    float val[8][PX];
    #pragma unroll
    for (int p = 0; p < PX; p++)
        #pragma unroll
        for (int jp = 0; jp < 4; jp++)
            unpack2(acc[p][jp], val[2*jp][p], val[2*jp+1][p]);

    const long hwout = (long)Hout * Wout;
    #pragma unroll
    for (int j = 0; j < 8; j++) {
        int oc = ocb + j;
        float b = bias[oc];
        #pragma unroll
        for (int q = 0; q < PX / 4; q++) {
            float4 o = make_float4(val[j][4*q+0] + b, val[j][4*q+1] + b,
                                   val[j][4*q+2] + b, val[j][4*q+3] + b);
            *(float4*)&y[((long)bb * Cout + oc) * hwout + (long)oh * Wout + ow0 + 4*q] = o;
        }
    }
}

// ---------------------------------------------------------------------------
// Stage-1 strided conv (Cin=1), batched over ALL 12 timesteps in one launch.
// grid = (4, 4, 12 * 8 * 16): z = (t*8 + b)*16 + ocg
// ---------------------------------------------------------------------------
__global__ __launch_bounds__(256) void conv4s2_c1_all_kernel(
    const float* __restrict__ x, long xbstride,
    const float* __restrict__ w, const float* __restrict__ bias,
    float* __restrict__ y)
{
    const int Hin = 128, Win = 128, Hout = 64, Wout = 64, Cout = 64;
    const int bx = blockIdx.x, by = blockIdx.y;
    const int ocg = blockIdx.z & 15;
    const int rem = blockIdx.z >> 4;
    const int bb = rem & 7;
    const int t  = rem >> 3;
    const int tx = threadIdx.x, ty = threadIdx.y;
    const int tid = ty * 16 + tx;
    const int oh = by * 16 + ty, ow = bx * 16 + tx;

    __shared__ float s_in[34 * 34];
    __shared__ float4 s_w4[16];

    float a0 = 0.f, a1 = 0.f, a2 = 0.f, a3 = 0.f;
    const int ih0 = by * 32 - 1, iw0 = bx * 32 - 1;
    const int oc0 = ocg * 4;
    const float* xc = x + (long)t * Hin * Win + (long)bb * xbstride;

    for (int i = tid; i < 34 * 34; i += 256) {
        int r = i / 34, c = i - r * 34;
        int ih = ih0 + r, iw = iw0 + c;
        float v = 0.f;
        if ((unsigned)ih < (unsigned)Hin && (unsigned)iw < (unsigned)Win)
            v = xc[ih * Win + iw];
        s_in[i] = v;
    }
    if (tid < 64) {
        int k = tid >> 2, j = tid & 3;
        ((float*)s_w4)[k * 4 + j] = w[(oc0 + j) * 16 + k];
    }
    __syncthreads();
    #pragma unroll
    for (int kh = 0; kh < 4; kh++)
        #pragma unroll
        for (int kw = 0; kw < 4; kw++) {
            float v = s_in[(2 * ty + kh) * 34 + 2 * tx + kw];
            float4 wv = s_w4[kh * 4 + kw];
            a0 += v * wv.x; a1 += v * wv.y; a2 += v * wv.z; a3 += v * wv.w;
        }
    const long cs = (long)Hout * Wout;
    long base = (long)t * S1_N + (((long)bb * Cout + oc0) * Hout + oh) * Wout + ow;
    y[base] = a0 + bias[oc0];           y[base + cs] = a1 + bias[oc0 + 1];
    y[base + 2 * cs] = a2 + bias[oc0 + 2]; y[base + 3 * cs] = a3 + bias[oc0 + 3];
}

__global__ void copyout_kernel(const float* __restrict__ a, int na,
                               const float* __restrict__ b, int nb,
                               const float* __restrict__ c, int nc,
                               float* __restrict__ out)
{
    int i = blockIdx.x * blockDim.x + threadIdx.x;
    if (i < na) out[i] = a[i];
    else if (i < na + nb) out[i] = b[i - na];
    else if (i < na + nb + nc) out[i] = c[i - na - nb];
}

extern "C" void kernel_launch(void* const* d_in, const int* in_sizes, int n_in,
                              void* d_out, int out_size)
{
    const float* input   = (const float*)d_in[0];
    const float* c1_w    = (const float*)d_in[1];
    const float* c1_b    = (const float*)d_in[2];
    const float* g1_zr_w = (const float*)d_in[3];
    const float* g1_zr_b = (const float*)d_in[4];
    const float* g1_h_w  = (const float*)d_in[5];
    const float* g1_h_b  = (const float*)d_in[6];
    const float* c2_w    = (const float*)d_in[7];
    const float* c2_b    = (const float*)d_in[8];
    const float* g2_zr_w = (const float*)d_in[9];
    const float* g2_zr_b = (const float*)d_in[10];
    const float* g2_h_w  = (const float*)d_in[11];
    const float* g2_h_b  = (const float*)d_in[12];
    const float* c3_w    = (const float*)d_in[13];
    const float* c3_b    = (const float*)d_in[14];
    const float* g3_zr_w = (const float*)d_in[15];
    const float* g3_zr_b = (const float*)d_in[16];
    const float* g3_h_w  = (const float*)d_in[17];
    const float* g3_h_b  = (const float*)d_in[18];

    float *h1, *x1b, *z1, *rh1, *h2, *x2, *z2, *rh2, *h3, *x3, *z3, *rh3;
    cudaGetSymbolAddress((void**)&h1, g_h1);   cudaGetSymbolAddress((void**)&x1b, g_x1b);
    cudaGetSymbolAddress((void**)&z1, g_z1);   cudaGetSymbolAddress((void**)&rh1, g_rh1);
    cudaGetSymbolAddress((void**)&h2, g_h2);   cudaGetSymbolAddress((void**)&x2, g_x2);
    cudaGetSymbolAddress((void**)&z2, g_z2);   cudaGetSymbolAddress((void**)&rh2, g_rh2);
    cudaGetSymbolAddress((void**)&h3, g_h3);   cudaGetSymbolAddress((void**)&x3, g_x3);
    cudaGetSymbolAddress((void**)&z3, g_z3);   cudaGetSymbolAddress((void**)&rh3, g_rh3);

    float *wt_c2, *wt_c3;
    cudaGetSymbolAddress((void**)&wt_c2, g_wt_c2);
    cudaGetSymbolAddress((void**)&wt_c3, g_wt_c3);
    unsigned *whzr1,*wlzr1,*whh1,*wlh1,*whzr2,*wlzr2,*whh2,*wlh2,*whzr3,*wlzr3,*whh3,*wlh3;
    cudaGetSymbolAddress((void**)&whzr1, g_wh_zr1); cudaGetSymbolAddress((void**)&wlzr1, g_wl_zr1);
    cudaGetSymbolAddress((void**)&whh1,  g_wh_h1);  cudaGetSymbolAddress((void**)&wlh1,  g_wl_h1);
    cudaGetSymbolAddress((void**)&whzr2, g_wh_zr2); cudaGetSymbolAddress((void**)&wlzr2, g_wl_zr2);
    cudaGetSymbolAddress((void**)&whh2,  g_wh_h2);  cudaGetSymbolAddress((void**)&wlh2,  g_wl_h2);
    cudaGetSymbolAddress((void**)&whzr3, g_wh_zr3); cudaGetSymbolAddress((void**)&wlzr3, g_wl_zr3);
    cudaGetSymbolAddress((void**)&whh3,  g_wh_h3);  cudaGetSymbolAddress((void**)&wlh3,  g_wl_h3);

    cudaFuncSetAttribute(conv5_mma_kernel<0,4>, cudaFuncAttributeMaxDynamicSharedMemorySize, C5_SMEM(4));
    cudaFuncSetAttribute(conv5_mma_kernel<1,4>, cudaFuncAttributeMaxDynamicSharedMemorySize, C5_SMEM(4));
    cudaFuncSetAttribute(conv5_mma_kernel<0,2>, cudaFuncAttributeMaxDynamicSharedMemorySize, C5_SMEM(2));
    cudaFuncSetAttribute(conv5_mma_kernel<1,2>, cudaFuncAttributeMaxDynamicSharedMemorySize, C5_SMEM(2));

    static cudaStream_t sA = nullptr, sB = nullptr, sC = nullptr;
    static cudaEvent_t evS, evA, evB, evC2, evC3, evE1, evE2, evE3;
    if (!sA) {
        cudaStreamCreateWithFlags(&sA, cudaStreamNonBlocking);
        cudaStreamCreateWithFlags(&sB, cudaStreamNonBlocking);
        cudaStreamCreateWithFlags(&sC, cudaStreamNonBlocking);
        cudaEventCreateWithFlags(&evS,  cudaEventDisableTiming);
        cudaEventCreateWithFlags(&evA,  cudaEventDisableTiming);
        cudaEventCreateWithFlags(&evB,  cudaEventDisableTiming);
        cudaEventCreateWithFlags(&evC2, cudaEventDisableTiming);
        cudaEventCreateWithFlags(&evC3, cudaEventDisableTiming);
        cudaEventCreateWithFlags(&evE1, cudaEventDisableTiming);
        cudaEventCreateWithFlags(&evE2, cudaEventDisableTiming);
        cudaEventCreateWithFlags(&evE3, cudaEventDisableTiming);
    }

    cudaMemsetAsync(h1, 0, (size_t)S1_N * sizeof(float), 0);
    cudaMemsetAsync(h2, 0, (size_t)S2_N * sizeof(float), 0);
    cudaMemsetAsync(h3, 0, (size_t)S3_N * sizeof(float), 0);

    auto tr = [](const float* w, float* wt, int Cin, int K, int Cout) {
        int n = Cout * Cin * K;
        transpose_w_kernel<<<(n + 255) / 256, 256>>>(w, wt, Cin, K, Cout);
    };
    tr(c2_w, wt_c2, 64, 16, 128);
    tr(c3_w, wt_c3, 128, 16, 128);
    auto wp = [](const float* w, unsigned* wh, unsigned* wl, int Cin, int Cout) {
        int n = (Cin / 2) * 25 * Cout;
        wpack_kernel<<<(n + 255) / 256, 256>>>(w, wh, wl, Cin, Cout);
    };
    wp(g1_zr_w, whzr1, wlzr1, 128, 128);
    wp(g1_h_w,  whh1,  wlh1,  128, 64);
    wp(g2_zr_w, whzr2, wlzr2, 256, 256);
    wp(g2_h_w,  whh2,  wlh2,  256, 128);
    wp(g3_zr_w, whzr3, wlzr3, 256, 256);
    wp(g3_h_w,  whh3,  wlh3,  256, 128);

    const long in_bstride = (long)12 * 128 * 128;   // T*H*W (C=1)
    // all 12 timesteps of c1 in one full-chip launch (no recurrent dependency)
    conv4s2_c1_all_kernel<<<dim3(4, 4, 12 * 8 * 16), dim3(16, 16)>>>(
        input, in_bstride, c1_w, c1_b, x1b);

    // fork the three stage streams off the capture stream
    cudaEventRecord(evS, 0);
    cudaStreamWaitEvent(sA, evS, 0);
    cudaStreamWaitEvent(sB, evS, 0);
    cudaStreamWaitEvent(sC, evS, 0);

    for (int t = 0; t < 12; t++) {
        const float* x1t = x1b + (long)t * S1_N;
        // ---- stream A: stage 1 (pure recurrent chain) ----
        conv5_mma_kernel<0,4><<<dim3(4, 4, 8 * 4), 256, C5_SMEM(4), sA>>>(
            x1t, h1, whzr1, wlzr1, g1_zr_b, z1, h1, rh1, 64, 64, 64);
        if (t > 0) cudaStreamWaitEvent(sA, evC2, 0);     // c2(t-1) finished reading h1
        conv5_mma_kernel<1,4><<<dim3(4, 4, 8 * 2), 256, C5_SMEM(4), sA>>>(
            x1t, rh1, whh1, wlh1, g1_h_b, z1, h1, nullptr, 64, 64, 64);
        cudaEventRecord(evA, sA);
        // ---- stream B: stage 2 ----
        cudaStreamWaitEvent(sB, evA, 0);                 // h1(t) ready
        conv4s2_kernel<4, 16><<<dim3(2, 2, 8 * 8), 128, 0, sB>>>(
            h1, wt_c2, c2_b, x2, 64, 128, 64, 64);
        cudaEventRecord(evC2, sB);                       // h1 consumed
        conv5_mma_kernel<0,4><<<dim3(2, 2, 8 * 8), 256, C5_SMEM(4), sB>>>(
            x2, h2, whzr2, wlzr2, g2_zr_b, z2, h2, rh2, 128, 32, 32);
        if (t > 0) cudaStreamWaitEvent(sB, evC3, 0);     // c3(t-1) finished reading h2
        conv5_mma_kernel<1,4><<<dim3(2, 2, 8 * 4), 256, C5_SMEM(4), sB>>>(
            x2, rh2, whh2, wlh2, g2_h_b, z2, h2, nullptr, 128, 32, 32);
        cudaEventRecord(evB, sB);
        // ---- stream C: stage 3 (NF=2) ----
        cudaStreamWaitEvent(sC, evB, 0);                 // h2(t) ready
        conv4s2_kernel<4, 16><<<dim3(1, 1, 8 * 8), 128, 0, sC>>>(
            h2, wt_c3, c3_b, x3, 128, 128, 32, 32);
        cudaEventRecord(evC3, sC);                       // h2 consumed
        conv5_mma_kernel<0,2><<<dim3(1, 1, 8 * 16), 256, C5_SMEM(2), sC>>>(
            x3, h3, whzr3, wlzr3, g3_zr_b, z3, h3, rh3, 128, 16, 16);
        conv5_mma_kernel<1,2><<<dim3(1, 1, 8 * 8), 256, C5_SMEM(2), sC>>>(
            x3, rh3, whh3, wlh3, g3_h_b, z3, h3, nullptr, 128, 16, 16);
    }

    // join all three streams back into the capture stream
    cudaEventRecord(evE1, sA);
    cudaEventRecord(evE2, sB);
    cudaEventRecord(evE3, sC);
    cudaStreamWaitEvent(0, evE1, 0);
    cudaStreamWaitEvent(0, evE2, 0);
    cudaStreamWaitEvent(0, evE3, 0);

    const int total = S1_N + S2_N + S3_N;
    copyout_kernel<<<(total + 255) / 256, 256>>>(h1, S1_N, h2, S2_N, h3, S3_N,
                                                 (float*)d_out);
}